// round 1
// baseline (speedup 1.0000x reference)
#include <cuda_runtime.h>
#include <math.h>

#define BATCH 256
#define DIM   512
#define LW    32
#define PIX   196
#define TT    8

// ---------------- scratch (static __device__ — allocation-guard safe) ----------------
__device__ float g_kT  [BATCH*PIX*DIM];   // k transposed to [B,P,D]
__device__ float g_bufA[BATCH*PIX*DIM];   // I, then ra
__device__ float g_bufB[BATCH*PIX*DIM];   // J = I_ * c_new
__device__ float g_cq  [BATCH*DIM];
__device__ float g_mI  [BATCH*DIM];
__device__ float g_r   [BATCH*DIM];
__device__ float g_mprev[BATCH*DIM];
__device__ float g_mm  [BATCH*DIM];
__device__ float g_msa [BATCH*DIM];
__device__ float g_tmp [BATCH*DIM];
__device__ float g_gate[BATCH];

// ---------------- reduction helpers ----------------
template<int NW>
__device__ __forceinline__ float blkSum(float v, float* red) {
    #pragma unroll
    for (int o = 16; o > 0; o >>= 1) v += __shfl_xor_sync(0xffffffffu, v, o);
    __syncthreads();
    if ((threadIdx.x & 31) == 0) red[threadIdx.x >> 5] = v;
    __syncthreads();
    float s = 0.f;
    #pragma unroll
    for (int i = 0; i < NW; i++) s += red[i];
    return s;
}

template<int NW>
__device__ __forceinline__ float blkMax(float v, float* red) {
    #pragma unroll
    for (int o = 16; o > 0; o >>= 1) v = fmaxf(v, __shfl_xor_sync(0xffffffffu, v, o));
    __syncthreads();
    if ((threadIdx.x & 31) == 0) red[threadIdx.x >> 5] = v;
    __syncthreads();
    float m = red[0];
    #pragma unroll
    for (int i = 1; i < NW; i++) m = fmaxf(m, red[i]);
    return m;
}

// ---------------- generic NT GEMM: C[m,n] = (sum_k A[m,k] * W[n,k] + bias[n]) * scale[(m/rpg), n] ----
// CONCAT: A is virtual [M, K] = [A0 | A1], each half K/2 wide, row-major.
// All dims must divide tile sizes exactly (true for this problem).
template<int BM, int BN, int BK, int TM, int TN, bool CONCAT>
__global__ void gemm_nt(const float* __restrict__ A0, const float* __restrict__ A1,
                        const float* __restrict__ W,  const float* __restrict__ bias,
                        const float* __restrict__ scale, float* __restrict__ C,
                        int M, int N, int K, int rpg)
{
    constexpr int TX = BN / TN, TY = BM / TM, THREADS = TX * TY;
    __shared__ __align__(16) float As[BK][BM];
    __shared__ __align__(16) float Bs[BK][BN];

    const int tid = threadIdx.x;
    const int bm = blockIdx.y * BM;
    const int bn = blockIdx.x * BN;
    const int tx = tid % TX;
    const int ty = tid / TX;
    const int halfK = K >> 1;

    float acc[TM][TN];
    #pragma unroll
    for (int i = 0; i < TM; i++)
        #pragma unroll
        for (int j = 0; j < TN; j++) acc[i][j] = 0.f;

    constexpr int ALD = (BM * BK) / (4 * THREADS);
    constexpr int BLD = (BN * BK) / (4 * THREADS);

    for (int k0 = 0; k0 < K; k0 += BK) {
        #pragma unroll
        for (int j = 0; j < ALD; j++) {
            int f  = tid + j * THREADS;
            int r  = f / (BK / 4);
            int c4 = (f % (BK / 4)) * 4;
            int gm = bm + r;
            int gk = k0 + c4;
            const float* src;
            if (CONCAT) {
                src = (gk < halfK) ? (A0 + (size_t)gm * halfK + gk)
                                   : (A1 + (size_t)gm * halfK + (gk - halfK));
            } else {
                src = A0 + (size_t)gm * K + gk;
            }
            float4 v = *reinterpret_cast<const float4*>(src);
            As[c4 + 0][r] = v.x; As[c4 + 1][r] = v.y;
            As[c4 + 2][r] = v.z; As[c4 + 3][r] = v.w;
        }
        #pragma unroll
        for (int j = 0; j < BLD; j++) {
            int f  = tid + j * THREADS;
            int r  = f / (BK / 4);
            int c4 = (f % (BK / 4)) * 4;
            int gn = bn + r;
            int gk = k0 + c4;
            float4 v = *reinterpret_cast<const float4*>(W + (size_t)gn * K + gk);
            Bs[c4 + 0][r] = v.x; Bs[c4 + 1][r] = v.y;
            Bs[c4 + 2][r] = v.z; Bs[c4 + 3][r] = v.w;
        }
        __syncthreads();
        #pragma unroll
        for (int kk = 0; kk < BK; kk++) {
            float a_[TM], b_[TN];
            #pragma unroll
            for (int i = 0; i < TM; i += 4)
                *reinterpret_cast<float4*>(&a_[i]) =
                    *reinterpret_cast<const float4*>(&As[kk][ty * TM + i]);
            #pragma unroll
            for (int i = 0; i < TN; i += 4)
                *reinterpret_cast<float4*>(&b_[i]) =
                    *reinterpret_cast<const float4*>(&Bs[kk][tx * TN + i]);
            #pragma unroll
            for (int i = 0; i < TM; i++)
                #pragma unroll
                for (int j = 0; j < TN; j++)
                    acc[i][j] = fmaf(a_[i], b_[j], acc[i][j]);
        }
        __syncthreads();
    }

    float bb[TN];
    #pragma unroll
    for (int j = 0; j < TN; j++) bb[j] = bias ? bias[bn + tx * TN + j] : 0.f;

    #pragma unroll
    for (int i = 0; i < TM; i++) {
        int gm = bm + ty * TM + i;
        const float* srow = scale ? (scale + (size_t)(gm / rpg) * N) : nullptr;
        float outv[TN];
        #pragma unroll
        for (int j = 0; j < TN; j++) {
            float v = acc[i][j] + bb[j];
            if (scale) v *= srow[bn + tx * TN + j];
            outv[j] = v;
        }
        #pragma unroll
        for (int j = 0; j < TN; j += 4)
            *reinterpret_cast<float4*>(&C[(size_t)gm * N + bn + tx * TN + j]) =
                *reinterpret_cast<const float4*>(&outv[j]);
    }
}

// ---------------- k [B,D,P] -> kT [B,P,D] ----------------
__global__ void transpose_k_kernel(const float* __restrict__ k, float* __restrict__ kT)
{
    __shared__ float tile[32][33];
    int b  = blockIdx.z;
    int p0 = blockIdx.x * 32;
    int c0 = blockIdx.y * 32;
    int tx = threadIdx.x, ty = threadIdx.y;
    #pragma unroll
    for (int j = 0; j < 32; j += 8) {
        int c = c0 + ty + j, p = p0 + tx;
        if (p < PIX) tile[ty + j][tx] = k[((size_t)b * DIM + c) * PIX + p];
    }
    __syncthreads();
    #pragma unroll
    for (int j = 0; j < 32; j += 8) {
        int p = p0 + ty + j, c = c0 + tx;
        if (p < PIX) kT[((size_t)b * PIX + p) * DIM + c] = tile[tx][ty + j];
    }
}

// ---------------- ControlUnit tail: ca -> mask -> softmax(L) -> cv, c_new ----------------
__global__ void control_kernel(const float* __restrict__ cq, const float* __restrict__ cw,
                               const int* __restrict__ mask, const float* __restrict__ Wca,
                               const float* __restrict__ bca,
                               float* __restrict__ cv_out, float* __restrict__ cnew)
{
    int b = blockIdx.x, tid = threadIdx.x;   // 256 threads
    __shared__ float u[DIM];
    __shared__ float s[LW];
    __shared__ float red[8];
    for (int d = tid; d < DIM; d += 256) u[d] = cq[(size_t)b * DIM + d] * Wca[d];
    __syncthreads();
    const float* cwb = cw + (size_t)b * LW * DIM;
    for (int l = 0; l < LW; l++) {
        float p = 0.f;
        for (int d = tid; d < DIM; d += 256) p += u[d] * cwb[(size_t)l * DIM + d];
        float tot = blkSum<8>(p, red);
        if (tid == 0) s[l] = (mask[b * LW + l] > 0) ? (tot + bca[0]) : -INFINITY;
    }
    __syncthreads();
    if (tid == 0) {
        float mx = -INFINITY;
        for (int l = 0; l < LW; l++) mx = fmaxf(mx, s[l]);
        float sm = 0.f;
        for (int l = 0; l < LW; l++) { float e = __expf(s[l] - mx); s[l] = e; sm += e; }
        float inv = 1.f / sm;
        for (int l = 0; l < LW; l++) { s[l] *= inv; cv_out[b * LW + l] = s[l]; }
    }
    __syncthreads();
    for (int d = tid; d < DIM; d += 256) {
        float a = 0.f;
        for (int l = 0; l < LW; l++) a = fmaf(s[l], cwb[(size_t)l * DIM + d], a);
        cnew[(size_t)b * DIM + d] = a;
    }
}

// ---------------- softmax over channels per pixel, rv (transposed write), r = sum_p rv*k ----------
__global__ void softmax_rv_kernel(const float* __restrict__ ra, const float* __restrict__ kT,
                                  float* __restrict__ rv_out, float* __restrict__ r_out)
{
    const int b = blockIdx.x, t = threadIdx.x;   // 512 threads, t = channel
    __shared__ float red[16];
    __shared__ float tile[14][513];
    const float* rab = ra + (size_t)b * PIX * DIM;
    const float* kTb = kT + (size_t)b * PIX * DIM;
    float* rvb = rv_out + (size_t)b * DIM * PIX;
    float racc = 0.f;
    for (int pp = 0; pp < 14; pp++) {           // 14 flush rounds x 14 pixels
        #pragma unroll 1
        for (int i = 0; i < 14; i++) {
            int p = pp * 14 + i;
            float x  = rab[(size_t)p * DIM + t];
            float mx = blkMax<16>(x, red);
            float e  = __expf(x - mx);
            float sm = blkSum<16>(e, red);
            float rv = e * (1.f / sm);
            tile[i][t] = rv;
            racc = fmaf(rv, kTb[(size_t)p * DIM + t], racc);
        }
        __syncthreads();
        int w = t >> 5, lane = t & 31;
        #pragma unroll 1
        for (int cc = 0; cc < 32; cc++) {
            int c = w * 32 + cc;
            if (lane < 14) rvb[(size_t)c * PIX + pp * 14 + lane] = tile[lane][c];
        }
        __syncthreads();
    }
    r_out[(size_t)b * DIM + t] = racc;
}

// ---------------- gate, sa softmax over T, m_sa ----------------
__global__ void gate_sa_kernel(const float* __restrict__ cnew, const float* __restrict__ Wc,
                               const float* __restrict__ bc,   const float* __restrict__ cs,
                               const float* __restrict__ Wsa,  const float* __restrict__ bsa,
                               const float* __restrict__ ms,
                               float* __restrict__ gate_out, float* __restrict__ msa_out)
{
    int b = blockIdx.x, tid = threadIdx.x;   // 256 threads
    __shared__ float red[8];
    __shared__ float sa[TT];
    __shared__ float gsh;
    float p = 0.f;
    for (int d = tid; d < DIM; d += 256) p += cnew[(size_t)b * DIM + d] * Wc[d];
    float tot = blkSum<8>(p, red);
    if (tid == 0) gsh = 1.f / (1.f + __expf(-(tot + bc[0])));
    __syncthreads();
    float gate = gsh;
    for (int t8 = 0; t8 < TT; t8++) {
        float q = 0.f;
        const float* csrow = cs + ((size_t)t8 * BATCH + b) * DIM;
        for (int d = tid; d < DIM; d += 256) q += csrow[d] * Wsa[d];
        float qt = blkSum<8>(q, red);
        if (tid == 0) sa[t8] = gate * qt + bsa[0];
    }
    __syncthreads();
    if (tid == 0) {
        float mx = -INFINITY;
        for (int i = 0; i < TT; i++) mx = fmaxf(mx, sa[i]);
        float sm = 0.f;
        for (int i = 0; i < TT; i++) { float e = __expf(sa[i] - mx); sa[i] = e; sm += e; }
        float inv = 1.f / sm;
        for (int i = 0; i < TT; i++) sa[i] *= inv;
    }
    __syncthreads();
    for (int d = tid; d < DIM; d += 256) {
        float a = 0.f;
        #pragma unroll
        for (int i = 0; i < TT; i++)
            a = fmaf(sa[i], ms[((size_t)i * BATCH + b) * DIM + d], a);
        msa_out[(size_t)b * DIM + d] = a;
    }
    if (tid == 0) gate_out[b] = gate;
}

// ---------------- final: m_new = g*m + (1-g)*(m_ + m_sa@Ws^T) ----------------
__global__ void final_kernel(const float* __restrict__ m, const float* __restrict__ mm,
                             const float* __restrict__ tmp, const float* __restrict__ gate,
                             float* __restrict__ mnew)
{
    int i = blockIdx.x * 256 + threadIdx.x;
    int b = i >> 9;
    float g = gate[b];
    mnew[i] = g * m[i] + (1.f - g) * (mm[i] + tmp[i]);
}

// ---------------- launch ----------------
extern "C" void kernel_launch(void* const* d_in, const int* in_sizes, int n_in,
                              void* d_out, int out_size)
{
    const float* c    = (const float*)d_in[0];
    const float* m    = (const float*)d_in[1];
    const float* k    = (const float*)d_in[2];
    const float* q    = (const float*)d_in[3];
    const float* cw   = (const float*)d_in[4];
    const int*   mask = (const int*)  d_in[5];
    const float* cs   = (const float*)d_in[6];
    const float* ms   = (const float*)d_in[7];
    const float* Wcq  = (const float*)d_in[8];
    const float* bcq  = (const float*)d_in[9];
    const float* Wca  = (const float*)d_in[10];
    const float* bca  = (const float*)d_in[11];
    const float* Wm_r = (const float*)d_in[12];
    const float* bm_r = (const float*)d_in[13];
    const float* Wk   = (const float*)d_in[14];
    const float* bk   = (const float*)d_in[15];
    const float* WI   = (const float*)d_in[16];
    const float* bI   = (const float*)d_in[17];
    const float* Wra  = (const float*)d_in[18];
    const float* bra  = (const float*)d_in[19];
    const float* Wm_w = (const float*)d_in[20];
    const float* bm_w = (const float*)d_in[21];
    const float* Wsa  = (const float*)d_in[22];
    const float* bsa  = (const float*)d_in[23];
    const float* Wm2  = (const float*)d_in[24];
    const float* bm2  = (const float*)d_in[25];
    const float* Wc   = (const float*)d_in[26];
    const float* bc   = (const float*)d_in[27];
    const float* Ws   = (const float*)d_in[28];

    float* out      = (float*)d_out;
    float* out_cnew = out;                       // [B,D]   131072
    float* out_mnew = out + 131072;              // [B,D]   131072
    float* out_cv   = out + 262144;              // [B,L]   8192
    float* out_rv   = out + 270336;              // [B,D,H,W] 25690112

    float *p_kT, *p_bufA, *p_bufB, *p_cq, *p_mI, *p_r, *p_mprev, *p_mm, *p_msa, *p_tmp, *p_gate;
    cudaGetSymbolAddress((void**)&p_kT,   g_kT);
    cudaGetSymbolAddress((void**)&p_bufA, g_bufA);
    cudaGetSymbolAddress((void**)&p_bufB, g_bufB);
    cudaGetSymbolAddress((void**)&p_cq,   g_cq);
    cudaGetSymbolAddress((void**)&p_mI,   g_mI);
    cudaGetSymbolAddress((void**)&p_r,    g_r);
    cudaGetSymbolAddress((void**)&p_mprev,g_mprev);
    cudaGetSymbolAddress((void**)&p_mm,   g_mm);
    cudaGetSymbolAddress((void**)&p_msa,  g_msa);
    cudaGetSymbolAddress((void**)&p_tmp,  g_tmp);
    cudaGetSymbolAddress((void**)&p_gate, g_gate);

    const int MBIG = BATCH * PIX;   // 50176

    // 1. kT = transpose(k)
    transpose_k_kernel<<<dim3(7, 16, BATCH), dim3(32, 8)>>>(k, p_kT);

    // 2. cq = [c|q] @ Wcq^T + bcq
    gemm_nt<64, 64, 16, 4, 4, true><<<dim3(8, 4), 256>>>(
        c, q, Wcq, bcq, nullptr, p_cq, BATCH, DIM, 2 * DIM, 1);

    // 3. ControlUnit tail -> cv, c_new (written directly into d_out)
    control_kernel<<<BATCH, 256>>>(p_cq, cw, mask, Wca, bca, out_cv, out_cnew);

    // 4. mI = m @ Wm_r^T + bm_r
    gemm_nt<64, 64, 16, 4, 4, false><<<dim3(8, 4), 256>>>(
        m, nullptr, Wm_r, bm_r, nullptr, p_mI, BATCH, DIM, DIM, 1);

    // 5. I = mI ⊙ (kT @ Wk^T + bk)          [B,P,D]
    gemm_nt<128, 128, 16, 8, 8, false><<<dim3(4, 392), 256>>>(
        p_kT, nullptr, Wk, bk, p_mI, p_bufA, MBIG, DIM, DIM, PIX);

    // 6. J = c_new ⊙ ([I|kT] @ WI^T + bI)   [B,P,D]
    gemm_nt<128, 128, 16, 8, 8, true><<<dim3(4, 392), 256>>>(
        p_bufA, p_kT, WI, bI, out_cnew, p_bufB, MBIG, DIM, 2 * DIM, PIX);

    // 7. ra = J @ Wra^T + bra               [B,P,D]  (reuse bufA)
    gemm_nt<128, 128, 16, 8, 8, false><<<dim3(4, 392), 256>>>(
        p_bufB, nullptr, Wra, bra, nullptr, p_bufA, MBIG, DIM, DIM, 1);

    // 8. rv = softmax_c(ra) -> d_out (transposed), r = sum_p rv*k
    softmax_rv_kernel<<<BATCH, 512>>>(p_bufA, p_kT, out_rv, p_r);

    // 9. m_prev = [r|m] @ Wm_w^T + bm_w
    gemm_nt<64, 64, 16, 4, 4, true><<<dim3(8, 4), 256>>>(
        p_r, m, Wm_w, bm_w, nullptr, p_mprev, BATCH, DIM, 2 * DIM, 1);

    // 10. m_ = m_prev @ Wm2^T + bm2
    gemm_nt<64, 64, 16, 4, 4, false><<<dim3(8, 4), 256>>>(
        p_mprev, nullptr, Wm2, bm2, nullptr, p_mm, BATCH, DIM, DIM, 1);

    // 11. gate, sa softmax, m_sa
    gate_sa_kernel<<<BATCH, 256>>>(out_cnew, Wc, bc, cs, Wsa, bsa, ms, p_gate, p_msa);

    // 12. tmp = m_sa @ Ws^T
    gemm_nt<64, 64, 16, 4, 4, false><<<dim3(8, 4), 256>>>(
        p_msa, nullptr, Ws, nullptr, nullptr, p_tmp, BATCH, DIM, DIM, 1);

    // 13. m_new = gate*m + (1-gate)*(m_ + tmp)
    final_kernel<<<(BATCH * DIM) / 256, 256>>>(m, p_mm, p_tmp, p_gate, out_mnew);
}

// round 3
// speedup vs baseline: 1.9756x; 1.9756x over previous
#include <cuda_runtime.h>
#include <cuda_bf16.h>
#include <math.h>
#include <stdint.h>

#define BATCH 256
#define DIM   512
#define LW    32
#define PIX   196
#define TT    8
#define MBIG  (BATCH*PIX)   // 50176

// ---------------- scratch (static __device__ — allocation-guard safe) ----------------
// hi/lo packed layout: [rows][2][512]  (hi at +0, lo at +512), row stride 1024
__device__ __nv_bfloat16 g_kT2[MBIG*1024];
__device__ __nv_bfloat16 g_I2 [MBIG*1024];
__device__ __nv_bfloat16 g_J2 [MBIG*1024];
__device__ float g_ra  [MBIG*DIM];
__device__ __nv_bfloat16 g_Wk2 [DIM*1024];   // [N][2][512]
__device__ __nv_bfloat16 g_WI2 [DIM*2048];   // [N][2][1024]
__device__ __nv_bfloat16 g_Wra2[DIM*1024];
__device__ float g_cq  [BATCH*DIM];
__device__ float g_mI  [BATCH*DIM];
__device__ float g_r   [BATCH*DIM];
__device__ float g_mprev[BATCH*DIM];
__device__ float g_mm  [BATCH*DIM];
__device__ float g_msa [BATCH*DIM];
__device__ float g_tmp [BATCH*DIM];
__device__ float g_gate[BATCH];

// ================= helpers =================
__device__ __forceinline__ uint32_t smem_u32(const void* p) {
    uint32_t a;
    asm("{ .reg .u64 t; cvta.to.shared.u64 t, %1; cvt.u32.u64 %0, t; }" : "=r"(a) : "l"(p));
    return a;
}
__device__ __forceinline__ void cpasync16(uint32_t dst, const void* src) {
    asm volatile("cp.async.cg.shared.global [%0], [%1], 16;" :: "r"(dst), "l"(src) : "memory");
}
__device__ __forceinline__ void cp_commit() { asm volatile("cp.async.commit_group;" ::: "memory"); }
__device__ __forceinline__ void cp_waitall() { asm volatile("cp.async.wait_all;" ::: "memory"); }

__device__ __forceinline__ void ldm_x4(uint32_t& r0, uint32_t& r1, uint32_t& r2, uint32_t& r3, uint32_t a) {
    asm volatile("ldmatrix.sync.aligned.m8n8.x4.shared.b16 {%0,%1,%2,%3}, [%4];"
                 : "=r"(r0), "=r"(r1), "=r"(r2), "=r"(r3) : "r"(a));
}
__device__ __forceinline__ void ldm_x2(uint32_t& r0, uint32_t& r1, uint32_t a) {
    asm volatile("ldmatrix.sync.aligned.m8n8.x2.shared.b16 {%0,%1}, [%2];"
                 : "=r"(r0), "=r"(r1) : "r"(a));
}
__device__ __forceinline__ void mma16816(float* c, uint32_t a0, uint32_t a1, uint32_t a2, uint32_t a3,
                                         uint32_t b0, uint32_t b1) {
    asm volatile("mma.sync.aligned.m16n8k16.row.col.f32.bf16.bf16.f32 "
                 "{%0,%1,%2,%3}, {%4,%5,%6,%7}, {%8,%9}, {%0,%1,%2,%3};"
                 : "+f"(c[0]), "+f"(c[1]), "+f"(c[2]), "+f"(c[3])
                 : "r"(a0), "r"(a1), "r"(a2), "r"(a3), "r"(b0), "r"(b1));
}

// ================= HMMA bf16-split GEMM =================
// C[m,n] = sum over 3 segments: Ah.Bh + Ah.Bl + Al.Bh  (A,W in [row][2][K] hi/lo layout)
// EPI 0: v = (acc + bias[n]) * scale[m/PIX, n] -> hi/lo bf16 into O[row][2][512]
// EPI 1: v = acc + bias[n] -> fp32 Of[m][n]
template<int K, bool CONCAT, int EPI>
__global__ void __launch_bounds__(256) mma_gemm(
    const __nv_bfloat16* __restrict__ A0, const __nv_bfloat16* __restrict__ A1,
    const __nv_bfloat16* __restrict__ W,
    const float* __restrict__ bias, const float* __restrict__ scale,
    __nv_bfloat16* __restrict__ O, float* __restrict__ Of)
{
    constexpr int SEGIT = K / 32;
    constexpr int ITERS = 3 * SEGIT;
    __shared__ __align__(128) char smem[32768];   // A: 2x8KB, B: 2x8KB
    const uint32_t sAu = smem_u32(smem);
    const uint32_t sBu = sAu + 16384u;

    const int tid = threadIdx.x, lane = tid & 31, wid = tid >> 5;
    const int bm = blockIdx.y * 128, bn = blockIdx.x * 128;
    const int wm = (wid >> 2) * 64, wn = (wid & 3) * 32;

    float acc[4][4][4];
    #pragma unroll
    for (int i = 0; i < 4; i++)
        #pragma unroll
        for (int j = 0; j < 4; j++)
            #pragma unroll
            for (int v = 0; v < 4; v++) acc[i][j][v] = 0.f;

    // loader lambda
    auto load_tiles = [&](int it, int buf) {
        int krel = it % SEGIT, seg = it / SEGIT;
        int acol = krel * 32, bcol = krel * 32;
        int apart = (seg == 2) ? 512 : 0;
        int bpart = (seg == 1) ? K : 0;
        const __nv_bfloat16* Asrc = A0;
        if (CONCAT && acol >= 512) { Asrc = A1; acol -= 512; }
        const int cc = tid & 3;
        #pragma unroll
        for (int j = 0; j < 2; j++) {
            int row = (tid >> 2) + j * 64;
            const __nv_bfloat16* g = Asrc + (size_t)(bm + row) * 1024 + apart + acol + cc * 8;
            uint32_t d = sAu + buf * 8192 + row * 64 + ((cc * 16) ^ (((row >> 1) & 3) << 4));
            cpasync16(d, g);
        }
        #pragma unroll
        for (int j = 0; j < 2; j++) {
            int row = (tid >> 2) + j * 64;
            const __nv_bfloat16* g = W + (size_t)(bn + row) * (2 * K) + bpart + bcol + cc * 8;
            uint32_t d = sBu + buf * 8192 + row * 64 + ((cc * 16) ^ (((row >> 1) & 3) << 4));
            cpasync16(d, g);
        }
    };

    load_tiles(0, 0);
    cp_commit();

    for (int it = 0; it < ITERS; ++it) {
        const int buf = it & 1;
        cp_waitall();
        __syncthreads();
        if (it + 1 < ITERS) { load_tiles(it + 1, buf ^ 1); cp_commit(); }

        const uint32_t sa = sAu + buf * 8192;
        const uint32_t sb = sBu + buf * 8192;
        #pragma unroll
        for (int kp = 0; kp < 2; kp++) {
            uint32_t af[4][4], bf[4][2];
            #pragma unroll
            for (int mi = 0; mi < 4; mi++) {
                int row = wm + mi * 16 + (lane & 15);
                int chunk = (kp * 2 + (lane >> 4)) ^ ((row >> 1) & 3);
                ldm_x4(af[mi][0], af[mi][1], af[mi][2], af[mi][3], sa + row * 64 + chunk * 16);
            }
            #pragma unroll
            for (int ni = 0; ni < 4; ni++) {
                int l = lane & 15;
                int nrow = wn + ni * 8 + (l & 7);
                int chunk = (kp * 2 + (l >> 3)) ^ ((nrow >> 1) & 3);
                ldm_x2(bf[ni][0], bf[ni][1], sb + nrow * 64 + chunk * 16);
            }
            #pragma unroll
            for (int mi = 0; mi < 4; mi++)
                #pragma unroll
                for (int ni = 0; ni < 4; ni++)
                    mma16816(acc[mi][ni], af[mi][0], af[mi][1], af[mi][2], af[mi][3],
                             bf[ni][0], bf[ni][1]);
        }
    }

    // ---------------- epilogue ----------------
    #pragma unroll
    for (int ni = 0; ni < 4; ni++) {
        const int n0 = bn + wn + ni * 8 + 2 * (lane & 3);
        const float b0 = bias[n0], b1 = bias[n0 + 1];
        #pragma unroll
        for (int mi = 0; mi < 4; mi++) {
            const int r0 = bm + wm + mi * 16 + (lane >> 2);
            const int r1 = r0 + 8;
            float* c = acc[mi][ni];
            if (EPI == 0) {
                const float* s0 = scale + (size_t)(r0 / PIX) * DIM;
                const float* s1 = scale + (size_t)(r1 / PIX) * DIM;
                float v00 = (c[0] + b0) * s0[n0], v01 = (c[1] + b1) * s0[n0 + 1];
                float v10 = (c[2] + b0) * s1[n0], v11 = (c[3] + b1) * s1[n0 + 1];
                __nv_bfloat16 h00 = __float2bfloat16(v00), h01 = __float2bfloat16(v01);
                __nv_bfloat16 h10 = __float2bfloat16(v10), h11 = __float2bfloat16(v11);
                uint32_t hi0 = (uint32_t)__bfloat16_as_ushort(h00) | ((uint32_t)__bfloat16_as_ushort(h01) << 16);
                uint32_t hi1 = (uint32_t)__bfloat16_as_ushort(h10) | ((uint32_t)__bfloat16_as_ushort(h11) << 16);
                __nv_bfloat16 l00 = __float2bfloat16(v00 - __bfloat162float(h00));
                __nv_bfloat16 l01 = __float2bfloat16(v01 - __bfloat162float(h01));
                __nv_bfloat16 l10 = __float2bfloat16(v10 - __bfloat162float(h10));
                __nv_bfloat16 l11 = __float2bfloat16(v11 - __bfloat162float(h11));
                uint32_t lo0 = (uint32_t)__bfloat16_as_ushort(l00) | ((uint32_t)__bfloat16_as_ushort(l01) << 16);
                uint32_t lo1 = (uint32_t)__bfloat16_as_ushort(l10) | ((uint32_t)__bfloat16_as_ushort(l11) << 16);
                *reinterpret_cast<uint32_t*>(O + (size_t)r0 * 1024 + n0)       = hi0;
                *reinterpret_cast<uint32_t*>(O + (size_t)r0 * 1024 + 512 + n0) = lo0;
                *reinterpret_cast<uint32_t*>(O + (size_t)r1 * 1024 + n0)       = hi1;
                *reinterpret_cast<uint32_t*>(O + (size_t)r1 * 1024 + 512 + n0) = lo1;
            } else {
                float2 v0 = make_float2(c[0] + b0, c[1] + b1);
                float2 v1 = make_float2(c[2] + b0, c[3] + b1);
                *reinterpret_cast<float2*>(Of + (size_t)r0 * DIM + n0) = v0;
                *reinterpret_cast<float2*>(Of + (size_t)r1 * DIM + n0) = v1;
            }
        }
    }
}

// ================= conversions =================
// weights -> [N][2][K] hi/lo
__global__ void split_w_kernel(const float* __restrict__ w, __nv_bfloat16* __restrict__ o, int N, int K)
{
    int i = blockIdx.x * 256 + threadIdx.x;
    if (i < N * K) {
        int n = i / K, k = i % K;
        float v = w[i];
        __nv_bfloat16 h = __float2bfloat16(v);
        o[(size_t)n * 2 * K + k]     = h;
        o[(size_t)n * 2 * K + K + k] = __float2bfloat16(v - __bfloat162float(h));
    }
}

// k [B,D,P] -> kT2 [B*P][2][512] hi/lo
__global__ void transpose_split_k(const float* __restrict__ k, __nv_bfloat16* __restrict__ kT2)
{
    __shared__ float tile[32][33];
    int b  = blockIdx.z;
    int p0 = blockIdx.x * 32;
    int c0 = blockIdx.y * 32;
    int tx = threadIdx.x, ty = threadIdx.y;
    #pragma unroll
    for (int j = 0; j < 32; j += 8) {
        int c = c0 + ty + j, p = p0 + tx;
        if (p < PIX) tile[ty + j][tx] = k[((size_t)b * DIM + c) * PIX + p];
    }
    __syncthreads();
    #pragma unroll
    for (int j = 0; j < 32; j += 8) {
        int p = p0 + ty + j, c = c0 + tx;
        if (p < PIX) {
            float v = tile[tx][ty + j];
            __nv_bfloat16 h = __float2bfloat16(v);
            size_t o = ((size_t)b * PIX + p) * 1024 + c;
            kT2[o]       = h;
            kT2[o + 512] = __float2bfloat16(v - __bfloat162float(h));
        }
    }
}

// ---------------- reduction helpers ----------------
template<int NW>
__device__ __forceinline__ float blkSum(float v, float* red) {
    #pragma unroll
    for (int o = 16; o > 0; o >>= 1) v += __shfl_xor_sync(0xffffffffu, v, o);
    __syncthreads();
    if ((threadIdx.x & 31) == 0) red[threadIdx.x >> 5] = v;
    __syncthreads();
    float s = 0.f;
    #pragma unroll
    for (int i = 0; i < NW; i++) s += red[i];
    return s;
}
template<int NW>
__device__ __forceinline__ float blkMax(float v, float* red) {
    #pragma unroll
    for (int o = 16; o > 0; o >>= 1) v = fmaxf(v, __shfl_xor_sync(0xffffffffu, v, o));
    __syncthreads();
    if ((threadIdx.x & 31) == 0) red[threadIdx.x >> 5] = v;
    __syncthreads();
    float m = red[0];
    #pragma unroll
    for (int i = 1; i < NW; i++) m = fmaxf(m, red[i]);
    return m;
}

// ---------------- fp32 NT GEMM (small M=256 GEMMs) ----------------
template<int BM, int BN, int BK, int TM, int TN, bool CONCAT>
__global__ void gemm_nt(const float* __restrict__ A0, const float* __restrict__ A1,
                        const float* __restrict__ W,  const float* __restrict__ bias,
                        const float* __restrict__ scale, float* __restrict__ C,
                        int M, int N, int K, int rpg)
{
    constexpr int TX = BN / TN, TY = BM / TM, THREADS = TX * TY;
    __shared__ __align__(16) float As[BK][BM];
    __shared__ __align__(16) float Bs[BK][BN];

    const int tid = threadIdx.x;
    const int bm = blockIdx.y * BM;
    const int bn = blockIdx.x * BN;
    const int tx = tid % TX;
    const int ty = tid / TX;
    const int halfK = K >> 1;

    float acc[TM][TN];
    #pragma unroll
    for (int i = 0; i < TM; i++)
        #pragma unroll
        for (int j = 0; j < TN; j++) acc[i][j] = 0.f;

    constexpr int ALD = (BM * BK) / (4 * THREADS);
    constexpr int BLD = (BN * BK) / (4 * THREADS);

    for (int k0 = 0; k0 < K; k0 += BK) {
        #pragma unroll
        for (int j = 0; j < ALD; j++) {
            int f  = tid + j * THREADS;
            int r  = f / (BK / 4);
            int c4 = (f % (BK / 4)) * 4;
            int gm = bm + r;
            int gk = k0 + c4;
            const float* src;
            if (CONCAT) {
                src = (gk < halfK) ? (A0 + (size_t)gm * halfK + gk)
                                   : (A1 + (size_t)gm * halfK + (gk - halfK));
            } else {
                src = A0 + (size_t)gm * K + gk;
            }
            float4 v = *reinterpret_cast<const float4*>(src);
            As[c4 + 0][r] = v.x; As[c4 + 1][r] = v.y;
            As[c4 + 2][r] = v.z; As[c4 + 3][r] = v.w;
        }
        #pragma unroll
        for (int j = 0; j < BLD; j++) {
            int f  = tid + j * THREADS;
            int r  = f / (BK / 4);
            int c4 = (f % (BK / 4)) * 4;
            int gn = bn + r;
            int gk = k0 + c4;
            float4 v = *reinterpret_cast<const float4*>(W + (size_t)gn * K + gk);
            Bs[c4 + 0][r] = v.x; Bs[c4 + 1][r] = v.y;
            Bs[c4 + 2][r] = v.z; Bs[c4 + 3][r] = v.w;
        }
        __syncthreads();
        #pragma unroll
        for (int kk = 0; kk < BK; kk++) {
            float a_[TM], b_[TN];
            #pragma unroll
            for (int i = 0; i < TM; i += 4)
                *reinterpret_cast<float4*>(&a_[i]) =
                    *reinterpret_cast<const float4*>(&As[kk][ty * TM + i]);
            #pragma unroll
            for (int i = 0; i < TN; i += 4)
                *reinterpret_cast<float4*>(&b_[i]) =
                    *reinterpret_cast<const float4*>(&Bs[kk][tx * TN + i]);
            #pragma unroll
            for (int i = 0; i < TM; i++)
                #pragma unroll
                for (int j = 0; j < TN; j++)
                    acc[i][j] = fmaf(a_[i], b_[j], acc[i][j]);
        }
        __syncthreads();
    }

    float bb[TN];
    #pragma unroll
    for (int j = 0; j < TN; j++) bb[j] = bias ? bias[bn + tx * TN + j] : 0.f;

    #pragma unroll
    for (int i = 0; i < TM; i++) {
        int gm = bm + ty * TM + i;
        float outv[TN];
        #pragma unroll
        for (int j = 0; j < TN; j++) outv[j] = acc[i][j] + bb[j];
        #pragma unroll
        for (int j = 0; j < TN; j += 4)
            *reinterpret_cast<float4*>(&C[(size_t)gm * N + bn + tx * TN + j]) =
                *reinterpret_cast<const float4*>(&outv[j]);
    }
}

// ---------------- ControlUnit tail ----------------
__global__ void control_kernel(const float* __restrict__ cq, const float* __restrict__ cw,
                               const int* __restrict__ mask, const float* __restrict__ Wca,
                               const float* __restrict__ bca,
                               float* __restrict__ cv_out, float* __restrict__ cnew)
{
    int b = blockIdx.x, tid = threadIdx.x;   // 256 threads
    __shared__ float u[DIM];
    __shared__ float s[LW];
    __shared__ float red[8];
    for (int d = tid; d < DIM; d += 256) u[d] = cq[(size_t)b * DIM + d] * Wca[d];
    __syncthreads();
    const float* cwb = cw + (size_t)b * LW * DIM;
    for (int l = 0; l < LW; l++) {
        float p = 0.f;
        for (int d = tid; d < DIM; d += 256) p += u[d] * cwb[(size_t)l * DIM + d];
        float tot = blkSum<8>(p, red);
        if (tid == 0) s[l] = (mask[b * LW + l] > 0) ? (tot + bca[0]) : -INFINITY;
    }
    __syncthreads();
    if (tid == 0) {
        float mx = -INFINITY;
        for (int l = 0; l < LW; l++) mx = fmaxf(mx, s[l]);
        float sm = 0.f;
        for (int l = 0; l < LW; l++) { float e = __expf(s[l] - mx); s[l] = e; sm += e; }
        float inv = 1.f / sm;
        for (int l = 0; l < LW; l++) { s[l] *= inv; cv_out[b * LW + l] = s[l]; }
    }
    __syncthreads();
    for (int d = tid; d < DIM; d += 256) {
        float a = 0.f;
        for (int l = 0; l < LW; l++) a = fmaf(s[l], cwb[(size_t)l * DIM + d], a);
        cnew[(size_t)b * DIM + d] = a;
    }
}

// ---------------- softmax over channels, rv (transposed), r = sum_p rv*k ----------
__global__ void softmax_rv_kernel(const float* __restrict__ ra,
                                  const __nv_bfloat16* __restrict__ kT2,
                                  float* __restrict__ rv_out, float* __restrict__ r_out)
{
    const int b = blockIdx.x, t = threadIdx.x;   // 512 threads, t = channel
    __shared__ float red[16];
    __shared__ float tile[14][513];
    const float* rab = ra + (size_t)b * PIX * DIM;
    const __nv_bfloat16* kb = kT2 + (size_t)b * PIX * 1024;
    float* rvb = rv_out + (size_t)b * DIM * PIX;
    float racc = 0.f;
    for (int pp = 0; pp < 14; pp++) {
        #pragma unroll 1
        for (int i = 0; i < 14; i++) {
            int p = pp * 14 + i;
            float x  = rab[(size_t)p * DIM + t];
            float mx = blkMax<16>(x, red);
            float e  = __expf(x - mx);
            float sm = blkSum<16>(e, red);
            float rv = e * (1.f / sm);
            tile[i][t] = rv;
            float kv = __bfloat162float(kb[(size_t)p * 1024 + t])
                     + __bfloat162float(kb[(size_t)p * 1024 + 512 + t]);
            racc = fmaf(rv, kv, racc);
        }
        __syncthreads();
        int w = t >> 5, lane = t & 31;
        #pragma unroll 1
        for (int cc = 0; cc < 32; cc++) {
            int c = w * 32 + cc;
            if (lane < 14) rvb[(size_t)c * PIX + pp * 14 + lane] = tile[lane][c];
        }
        __syncthreads();
    }
    r_out[(size_t)b * DIM + t] = racc;
}

// ---------------- gate, sa softmax over T, m_sa ----------------
__global__ void gate_sa_kernel(const float* __restrict__ cnew, const float* __restrict__ Wc,
                               const float* __restrict__ bc,   const float* __restrict__ cs,
                               const float* __restrict__ Wsa,  const float* __restrict__ bsa,
                               const float* __restrict__ ms,
                               float* __restrict__ gate_out, float* __restrict__ msa_out)
{
    int b = blockIdx.x, tid = threadIdx.x;   // 256 threads
    __shared__ float red[8];
    __shared__ float sa[TT];
    __shared__ float gsh;
    float p = 0.f;
    for (int d = tid; d < DIM; d += 256) p += cnew[(size_t)b * DIM + d] * Wc[d];
    float tot = blkSum<8>(p, red);
    if (tid == 0) gsh = 1.f / (1.f + __expf(-(tot + bc[0])));
    __syncthreads();
    float gate = gsh;
    for (int t8 = 0; t8 < TT; t8++) {
        float qv = 0.f;
        const float* csrow = cs + ((size_t)t8 * BATCH + b) * DIM;
        for (int d = tid; d < DIM; d += 256) qv += csrow[d] * Wsa[d];
        float qt = blkSum<8>(qv, red);
        if (tid == 0) sa[t8] = gate * qt + bsa[0];
    }
    __syncthreads();
    if (tid == 0) {
        float mx = -INFINITY;
        for (int i = 0; i < TT; i++) mx = fmaxf(mx, sa[i]);
        float sm = 0.f;
        for (int i = 0; i < TT; i++) { float e = __expf(sa[i] - mx); sa[i] = e; sm += e; }
        float inv = 1.f / sm;
        for (int i = 0; i < TT; i++) sa[i] *= inv;
    }
    __syncthreads();
    for (int d = tid; d < DIM; d += 256) {
        float a = 0.f;
        #pragma unroll
        for (int i = 0; i < TT; i++)
            a = fmaf(sa[i], ms[((size_t)i * BATCH + b) * DIM + d], a);
        msa_out[(size_t)b * DIM + d] = a;
    }
    if (tid == 0) gate_out[b] = gate;
}

// ---------------- final ----------------
__global__ void final_kernel(const float* __restrict__ m, const float* __restrict__ mm,
                             const float* __restrict__ tmp, const float* __restrict__ gate,
                             float* __restrict__ mnew)
{
    int i = blockIdx.x * 256 + threadIdx.x;
    int b = i >> 9;
    float g = gate[b];
    mnew[i] = g * m[i] + (1.f - g) * (mm[i] + tmp[i]);
}

// ---------------- launch ----------------
extern "C" void kernel_launch(void* const* d_in, const int* in_sizes, int n_in,
                              void* d_out, int out_size)
{
    const float* c    = (const float*)d_in[0];
    const float* m    = (const float*)d_in[1];
    const float* k    = (const float*)d_in[2];
    const float* q    = (const float*)d_in[3];
    const float* cw   = (const float*)d_in[4];
    const int*   mask = (const int*)  d_in[5];
    const float* cs   = (const float*)d_in[6];
    const float* ms   = (const float*)d_in[7];
    const float* Wcq  = (const float*)d_in[8];
    const float* bcq  = (const float*)d_in[9];
    const float* Wca  = (const float*)d_in[10];
    const float* bca  = (const float*)d_in[11];
    const float* Wm_r = (const float*)d_in[12];
    const float* bm_r = (const float*)d_in[13];
    const float* Wk   = (const float*)d_in[14];
    const float* bk   = (const float*)d_in[15];
    const float* WI   = (const float*)d_in[16];
    const float* bI   = (const float*)d_in[17];
    const float* Wra  = (const float*)d_in[18];
    const float* bra  = (const float*)d_in[19];
    const float* Wm_w = (const float*)d_in[20];
    const float* bm_w = (const float*)d_in[21];
    const float* Wsa  = (const float*)d_in[22];
    const float* bsa  = (const float*)d_in[23];
    const float* Wm2  = (const float*)d_in[24];
    const float* bm2  = (const float*)d_in[25];
    const float* Wc   = (const float*)d_in[26];
    const float* bc   = (const float*)d_in[27];
    const float* Ws   = (const float*)d_in[28];

    float* out      = (float*)d_out;
    float* out_cnew = out;                       // [B,D]
    float* out_mnew = out + 131072;              // [B,D]
    float* out_cv   = out + 262144;              // [B,L]
    float* out_rv   = out + 270336;              // [B,D,H,W]

    __nv_bfloat16 *p_kT2, *p_I2, *p_J2, *p_Wk2, *p_WI2, *p_Wra2;
    float *p_ra, *p_cq, *p_mI, *p_r, *p_mprev, *p_mm, *p_msa, *p_tmp, *p_gate;
    cudaGetSymbolAddress((void**)&p_kT2,  g_kT2);
    cudaGetSymbolAddress((void**)&p_I2,   g_I2);
    cudaGetSymbolAddress((void**)&p_J2,   g_J2);
    cudaGetSymbolAddress((void**)&p_Wk2,  g_Wk2);
    cudaGetSymbolAddress((void**)&p_WI2,  g_WI2);
    cudaGetSymbolAddress((void**)&p_Wra2, g_Wra2);
    cudaGetSymbolAddress((void**)&p_ra,   g_ra);
    cudaGetSymbolAddress((void**)&p_cq,   g_cq);
    cudaGetSymbolAddress((void**)&p_mI,   g_mI);
    cudaGetSymbolAddress((void**)&p_r,    g_r);
    cudaGetSymbolAddress((void**)&p_mprev,g_mprev);
    cudaGetSymbolAddress((void**)&p_mm,   g_mm);
    cudaGetSymbolAddress((void**)&p_msa,  g_msa);
    cudaGetSymbolAddress((void**)&p_tmp,  g_tmp);
    cudaGetSymbolAddress((void**)&p_gate, g_gate);

    // 0. conversions: weights hi/lo; k -> kT hi/lo
    split_w_kernel<<<(DIM*DIM + 255)/256, 256>>>(Wk,  p_Wk2,  DIM, DIM);
    split_w_kernel<<<(DIM*2*DIM + 255)/256, 256>>>(WI, p_WI2, DIM, 2*DIM);
    split_w_kernel<<<(DIM*DIM + 255)/256, 256>>>(Wra, p_Wra2, DIM, DIM);
    transpose_split_k<<<dim3(7, 16, BATCH), dim3(32, 8)>>>(k, p_kT2);

    // 1. cq = [c|q] @ Wcq^T + bcq
    gemm_nt<64, 64, 16, 4, 4, true><<<dim3(8, 4), 256>>>(
        c, q, Wcq, bcq, nullptr, p_cq, BATCH, DIM, 2 * DIM, 1);

    // 2. ControlUnit tail -> cv, c_new
    control_kernel<<<BATCH, 256>>>(p_cq, cw, mask, Wca, bca, out_cv, out_cnew);

    // 3. mI = m @ Wm_r^T + bm_r
    gemm_nt<64, 64, 16, 4, 4, false><<<dim3(8, 4), 256>>>(
        m, nullptr, Wm_r, bm_r, nullptr, p_mI, BATCH, DIM, DIM, 1);

    // 4. I = mI ⊙ (kT @ Wk^T + bk) -> hi/lo          [HMMA]
    mma_gemm<512, false, 0><<<dim3(4, 392), 256>>>(
        p_kT2, nullptr, p_Wk2, bk, p_mI, p_I2, nullptr);

    // 5. J = c_new ⊙ ([I|kT] @ WI^T + bI) -> hi/lo   [HMMA]
    mma_gemm<1024, true, 0><<<dim3(4, 392), 256>>>(
        p_I2, p_kT2, p_WI2, bI, out_cnew, p_J2, nullptr);

    // 6. ra = J @ Wra^T + bra -> fp32                [HMMA]
    mma_gemm<512, false, 1><<<dim3(4, 392), 256>>>(
        p_J2, nullptr, p_Wra2, bra, nullptr, nullptr, p_ra);

    // 7. rv = softmax_c(ra) -> d_out (transposed), r = sum_p rv*k
    softmax_rv_kernel<<<BATCH, 512>>>(p_ra, p_kT2, out_rv, p_r);

    // 8. m_prev = [r|m] @ Wm_w^T + bm_w
    gemm_nt<64, 64, 16, 4, 4, true><<<dim3(8, 4), 256>>>(
        p_r, m, Wm_w, bm_w, nullptr, p_mprev, BATCH, DIM, 2 * DIM, 1);

    // 9. m_ = m_prev @ Wm2^T + bm2
    gemm_nt<64, 64, 16, 4, 4, false><<<dim3(8, 4), 256>>>(
        p_mprev, nullptr, Wm2, bm2, nullptr, p_mm, BATCH, DIM, DIM, 1);

    // 10. gate, sa softmax, m_sa
    gate_sa_kernel<<<BATCH, 256>>>(out_cnew, Wc, bc, cs, Wsa, bsa, ms, p_gate, p_msa);

    // 11. tmp = m_sa @ Ws^T
    gemm_nt<64, 64, 16, 4, 4, false><<<dim3(8, 4), 256>>>(
        p_msa, nullptr, Ws, nullptr, nullptr, p_tmp, BATCH, DIM, DIM, 1);

    // 12. m_new = gate*m + (1-gate)*(m_ + tmp)
    final_kernel<<<(BATCH * DIM) / 256, 256>>>(m, p_mm, p_tmp, p_gate, out_mnew);
}

// round 4
// speedup vs baseline: 2.7432x; 1.3886x over previous
#include <cuda_runtime.h>
#include <cuda_bf16.h>
#include <math.h>
#include <stdint.h>

#define BATCH 256
#define DIM   512
#define LW    32
#define PIX   196
#define TT    8
#define MBIG  (BATCH*PIX)   // 50176

// ---------------- scratch (static __device__ — allocation-guard safe) ----------------
// hi/lo packed layout: [rows][2][512]  (hi at +0, lo at +512), row stride 1024
__device__ __nv_bfloat16 g_kT2[MBIG*1024];
__device__ __nv_bfloat16 g_I2 [MBIG*1024];
__device__ __nv_bfloat16 g_J2 [MBIG*1024];
__device__ float g_ra  [MBIG*DIM];
__device__ __nv_bfloat16 g_Wk2 [DIM*1024];   // [N][2][512]
__device__ __nv_bfloat16 g_WI2 [DIM*2048];   // [N][2][1024]
__device__ __nv_bfloat16 g_Wra2[DIM*1024];
__device__ float g_cq  [BATCH*DIM];
__device__ float g_mI  [BATCH*DIM];
__device__ float g_r   [BATCH*DIM];
__device__ float g_mprev[BATCH*DIM];
__device__ float g_mm  [BATCH*DIM];
__device__ float g_msa [BATCH*DIM];
__device__ float g_tmp [BATCH*DIM];
__device__ float g_gate[BATCH];

// ================= helpers =================
__device__ __forceinline__ uint32_t smem_u32(const void* p) {
    uint32_t a;
    asm("{ .reg .u64 t; cvta.to.shared.u64 t, %1; cvt.u32.u64 %0, t; }" : "=r"(a) : "l"(p));
    return a;
}
__device__ __forceinline__ void cpasync16(uint32_t dst, const void* src) {
    asm volatile("cp.async.cg.shared.global [%0], [%1], 16;" :: "r"(dst), "l"(src) : "memory");
}
__device__ __forceinline__ void cp_commit() { asm volatile("cp.async.commit_group;" ::: "memory"); }
__device__ __forceinline__ void cp_wait1() { asm volatile("cp.async.wait_group 1;" ::: "memory"); }
__device__ __forceinline__ void cp_wait0() { asm volatile("cp.async.wait_group 0;" ::: "memory"); }

__device__ __forceinline__ void ldm_x4(uint32_t& r0, uint32_t& r1, uint32_t& r2, uint32_t& r3, uint32_t a) {
    asm volatile("ldmatrix.sync.aligned.m8n8.x4.shared.b16 {%0,%1,%2,%3}, [%4];"
                 : "=r"(r0), "=r"(r1), "=r"(r2), "=r"(r3) : "r"(a));
}
__device__ __forceinline__ void ldm_x2(uint32_t& r0, uint32_t& r1, uint32_t a) {
    asm volatile("ldmatrix.sync.aligned.m8n8.x2.shared.b16 {%0,%1}, [%2];"
                 : "=r"(r0), "=r"(r1) : "r"(a));
}
__device__ __forceinline__ void mma16816(float* c, const uint32_t* a, const uint32_t* b) {
    asm volatile("mma.sync.aligned.m16n8k16.row.col.f32.bf16.bf16.f32 "
                 "{%0,%1,%2,%3}, {%4,%5,%6,%7}, {%8,%9}, {%0,%1,%2,%3};"
                 : "+f"(c[0]), "+f"(c[1]), "+f"(c[2]), "+f"(c[3])
                 : "r"(a[0]), "r"(a[1]), "r"(a[2]), "r"(a[3]), "r"(b[0]), "r"(b[1]));
}

// ================= HMMA bf16-split GEMM v2 =================
// Per K-step loads Ah,Al,Bh,Bl tiles once; issues 3 combos (AhBh + AhBl + AlBh).
// 3-stage cp.async ring, 32KB/stage, wait_group 1.
// EPI 0: v = (acc + bias[n]) * scale[m/PIX, n] -> hi/lo bf16 into O[row][2][512]
// EPI 1: v = acc + bias[n] -> fp32 Of[m][n]
#define MG_SMEM (3*32768)

template<int K, bool CONCAT, int EPI>
__global__ void __launch_bounds__(256) mma_gemm(
    const __nv_bfloat16* __restrict__ A0, const __nv_bfloat16* __restrict__ A1,
    const __nv_bfloat16* __restrict__ W,
    const float* __restrict__ bias, const float* __restrict__ scale,
    __nv_bfloat16* __restrict__ O, float* __restrict__ Of)
{
    constexpr int KIT = K / 32;
    extern __shared__ __align__(128) char dsm[];
    const uint32_t smb = smem_u32(dsm);

    const int tid = threadIdx.x, lane = tid & 31, wid = tid >> 5;
    const int bm = blockIdx.y * 128, bn = blockIdx.x * 128;
    const int wm = (wid >> 2) * 64, wn = (wid & 3) * 32;

    float acc[4][4][4];
    #pragma unroll
    for (int i = 0; i < 4; i++)
        #pragma unroll
        for (int j = 0; j < 4; j++)
            #pragma unroll
            for (int v = 0; v < 4; v++) acc[i][j][v] = 0.f;

    auto load_stage = [&](int it, int stage) {
        uint32_t sb = smb + (uint32_t)stage * 32768u;
        int k0 = it * 32;
        const __nv_bfloat16* Asrc = A0;
        int ac = k0;
        if (CONCAT && k0 >= 512) { Asrc = A1; ac = k0 - 512; }
        const int cc = tid & 3;
        #pragma unroll
        for (int j = 0; j < 2; j++) {
            int row = (tid >> 2) + j * 64;
            uint32_t d = sb + row * 64 + ((cc * 16) ^ (((row >> 1) & 3) << 4));
            const __nv_bfloat16* ga = Asrc + (size_t)(bm + row) * 1024 + ac + cc * 8;
            cpasync16(d,          ga);          // A_hi
            cpasync16(d + 8192u,  ga + 512);    // A_lo
            const __nv_bfloat16* gw = W + (size_t)(bn + row) * (2 * K) + k0 + cc * 8;
            cpasync16(d + 16384u, gw);          // B_hi
            cpasync16(d + 24576u, gw + K);      // B_lo
        }
    };

    load_stage(0, 0); cp_commit();
    if (KIT > 1) { load_stage(1, 1); cp_commit(); }

    for (int it = 0; it < KIT; ++it) {
        if (it + 1 < KIT) cp_wait1(); else cp_wait0();
        __syncthreads();
        if (it + 2 < KIT) { load_stage(it + 2, (it + 2) % 3); cp_commit(); }

        uint32_t sb  = smb + (uint32_t)(it % 3) * 32768u;
        uint32_t sAh = sb, sAl = sb + 8192u, sBh = sb + 16384u, sBl = sb + 24576u;
        #pragma unroll
        for (int kp = 0; kp < 2; kp++) {
            uint32_t ah[4][4], al[4][4], bh[4][2], bl[4][2];
            #pragma unroll
            for (int mi = 0; mi < 4; mi++) {
                int row = wm + mi * 16 + (lane & 15);
                int chunk = (kp * 2 + (lane >> 4)) ^ ((row >> 1) & 3);
                uint32_t off = row * 64 + chunk * 16;
                ldm_x4(ah[mi][0], ah[mi][1], ah[mi][2], ah[mi][3], sAh + off);
                ldm_x4(al[mi][0], al[mi][1], al[mi][2], al[mi][3], sAl + off);
            }
            #pragma unroll
            for (int ni = 0; ni < 4; ni++) {
                int l = lane & 15;
                int nrow = wn + ni * 8 + (l & 7);
                int chunk = (kp * 2 + (l >> 3)) ^ ((nrow >> 1) & 3);
                uint32_t off = nrow * 64 + chunk * 16;
                ldm_x2(bh[ni][0], bh[ni][1], sBh + off);
                ldm_x2(bl[ni][0], bl[ni][1], sBl + off);
            }
            #pragma unroll
            for (int mi = 0; mi < 4; mi++)
                #pragma unroll
                for (int ni = 0; ni < 4; ni++)
                    mma16816(acc[mi][ni], ah[mi], bh[ni]);
            #pragma unroll
            for (int mi = 0; mi < 4; mi++)
                #pragma unroll
                for (int ni = 0; ni < 4; ni++)
                    mma16816(acc[mi][ni], ah[mi], bl[ni]);
            #pragma unroll
            for (int mi = 0; mi < 4; mi++)
                #pragma unroll
                for (int ni = 0; ni < 4; ni++)
                    mma16816(acc[mi][ni], al[mi], bh[ni]);
        }
        __syncthreads();
    }

    // ---------------- epilogue ----------------
    #pragma unroll
    for (int ni = 0; ni < 4; ni++) {
        const int n0 = bn + wn + ni * 8 + 2 * (lane & 3);
        const float b0 = bias[n0], b1 = bias[n0 + 1];
        #pragma unroll
        for (int mi = 0; mi < 4; mi++) {
            const int r0 = bm + wm + mi * 16 + (lane >> 2);
            const int r1 = r0 + 8;
            float* c = acc[mi][ni];
            if (EPI == 0) {
                const float* s0 = scale + (size_t)(r0 / PIX) * DIM;
                const float* s1 = scale + (size_t)(r1 / PIX) * DIM;
                float v00 = (c[0] + b0) * s0[n0], v01 = (c[1] + b1) * s0[n0 + 1];
                float v10 = (c[2] + b0) * s1[n0], v11 = (c[3] + b1) * s1[n0 + 1];
                __nv_bfloat16 h00 = __float2bfloat16(v00), h01 = __float2bfloat16(v01);
                __nv_bfloat16 h10 = __float2bfloat16(v10), h11 = __float2bfloat16(v11);
                uint32_t hi0 = (uint32_t)__bfloat16_as_ushort(h00) | ((uint32_t)__bfloat16_as_ushort(h01) << 16);
                uint32_t hi1 = (uint32_t)__bfloat16_as_ushort(h10) | ((uint32_t)__bfloat16_as_ushort(h11) << 16);
                __nv_bfloat16 l00 = __float2bfloat16(v00 - __bfloat162float(h00));
                __nv_bfloat16 l01 = __float2bfloat16(v01 - __bfloat162float(h01));
                __nv_bfloat16 l10 = __float2bfloat16(v10 - __bfloat162float(h10));
                __nv_bfloat16 l11 = __float2bfloat16(v11 - __bfloat162float(h11));
                uint32_t lo0 = (uint32_t)__bfloat16_as_ushort(l00) | ((uint32_t)__bfloat16_as_ushort(l01) << 16);
                uint32_t lo1 = (uint32_t)__bfloat16_as_ushort(l10) | ((uint32_t)__bfloat16_as_ushort(l11) << 16);
                *reinterpret_cast<uint32_t*>(O + (size_t)r0 * 1024 + n0)       = hi0;
                *reinterpret_cast<uint32_t*>(O + (size_t)r0 * 1024 + 512 + n0) = lo0;
                *reinterpret_cast<uint32_t*>(O + (size_t)r1 * 1024 + n0)       = hi1;
                *reinterpret_cast<uint32_t*>(O + (size_t)r1 * 1024 + 512 + n0) = lo1;
            } else {
                float2 v0 = make_float2(c[0] + b0, c[1] + b1);
                float2 v1 = make_float2(c[2] + b0, c[3] + b1);
                *reinterpret_cast<float2*>(Of + (size_t)r0 * DIM + n0) = v0;
                *reinterpret_cast<float2*>(Of + (size_t)r1 * DIM + n0) = v1;
            }
        }
    }
}

// ================= conversions =================
// weights -> [N][2][K] hi/lo
__global__ void split_w_kernel(const float* __restrict__ w, __nv_bfloat16* __restrict__ o, int N, int K)
{
    int i = blockIdx.x * 256 + threadIdx.x;
    if (i < N * K) {
        int n = i / K, k = i % K;
        float v = w[i];
        __nv_bfloat16 h = __float2bfloat16(v);
        o[(size_t)n * 2 * K + k]     = h;
        o[(size_t)n * 2 * K + K + k] = __float2bfloat16(v - __bfloat162float(h));
    }
}

// k [B,D,P] -> kT2 [B*P][2][512] hi/lo
__global__ void transpose_split_k(const float* __restrict__ k, __nv_bfloat16* __restrict__ kT2)
{
    __shared__ float tile[32][33];
    int b  = blockIdx.z;
    int p0 = blockIdx.x * 32;
    int c0 = blockIdx.y * 32;
    int tx = threadIdx.x, ty = threadIdx.y;
    #pragma unroll
    for (int j = 0; j < 32; j += 8) {
        int c = c0 + ty + j, p = p0 + tx;
        if (p < PIX) tile[ty + j][tx] = k[((size_t)b * DIM + c) * PIX + p];
    }
    __syncthreads();
    #pragma unroll
    for (int j = 0; j < 32; j += 8) {
        int p = p0 + ty + j, c = c0 + tx;
        if (p < PIX) {
            float v = tile[tx][ty + j];
            __nv_bfloat16 h = __float2bfloat16(v);
            size_t o = ((size_t)b * PIX + p) * 1024 + c;
            kT2[o]       = h;
            kT2[o + 512] = __float2bfloat16(v - __bfloat162float(h));
        }
    }
}

// ---------------- reduction helpers ----------------
template<int NW>
__device__ __forceinline__ float blkSum(float v, float* red) {
    #pragma unroll
    for (int o = 16; o > 0; o >>= 1) v += __shfl_xor_sync(0xffffffffu, v, o);
    __syncthreads();
    if ((threadIdx.x & 31) == 0) red[threadIdx.x >> 5] = v;
    __syncthreads();
    float s = 0.f;
    #pragma unroll
    for (int i = 0; i < NW; i++) s += red[i];
    return s;
}

// ---------------- fp32 NT GEMM (small M=256 GEMMs) ----------------
template<int BM, int BN, int BK, int TM, int TN, bool CONCAT>
__global__ void gemm_nt(const float* __restrict__ A0, const float* __restrict__ A1,
                        const float* __restrict__ W,  const float* __restrict__ bias,
                        const float* __restrict__ scale, float* __restrict__ C,
                        int M, int N, int K, int rpg)
{
    constexpr int TX = BN / TN, TY = BM / TM, THREADS = TX * TY;
    __shared__ __align__(16) float As[BK][BM];
    __shared__ __align__(16) float Bs[BK][BN];

    const int tid = threadIdx.x;
    const int bm = blockIdx.y * BM;
    const int bn = blockIdx.x * BN;
    const int tx = tid % TX;
    const int ty = tid / TX;
    const int halfK = K >> 1;

    float acc[TM][TN];
    #pragma unroll
    for (int i = 0; i < TM; i++)
        #pragma unroll
        for (int j = 0; j < TN; j++) acc[i][j] = 0.f;

    constexpr int ALD = (BM * BK) / (4 * THREADS);
    constexpr int BLD = (BN * BK) / (4 * THREADS);

    for (int k0 = 0; k0 < K; k0 += BK) {
        #pragma unroll
        for (int j = 0; j < ALD; j++) {
            int f  = tid + j * THREADS;
            int r  = f / (BK / 4);
            int c4 = (f % (BK / 4)) * 4;
            int gm = bm + r;
            int gk = k0 + c4;
            const float* src;
            if (CONCAT) {
                src = (gk < halfK) ? (A0 + (size_t)gm * halfK + gk)
                                   : (A1 + (size_t)gm * halfK + (gk - halfK));
            } else {
                src = A0 + (size_t)gm * K + gk;
            }
            float4 v = *reinterpret_cast<const float4*>(src);
            As[c4 + 0][r] = v.x; As[c4 + 1][r] = v.y;
            As[c4 + 2][r] = v.z; As[c4 + 3][r] = v.w;
        }
        #pragma unroll
        for (int j = 0; j < BLD; j++) {
            int f  = tid + j * THREADS;
            int r  = f / (BK / 4);
            int c4 = (f % (BK / 4)) * 4;
            int gn = bn + r;
            int gk = k0 + c4;
            float4 v = *reinterpret_cast<const float4*>(W + (size_t)gn * K + gk);
            Bs[c4 + 0][r] = v.x; Bs[c4 + 1][r] = v.y;
            Bs[c4 + 2][r] = v.z; Bs[c4 + 3][r] = v.w;
        }
        __syncthreads();
        #pragma unroll
        for (int kk = 0; kk < BK; kk++) {
            float a_[TM], b_[TN];
            #pragma unroll
            for (int i = 0; i < TM; i += 4)
                *reinterpret_cast<float4*>(&a_[i]) =
                    *reinterpret_cast<const float4*>(&As[kk][ty * TM + i]);
            #pragma unroll
            for (int i = 0; i < TN; i += 4)
                *reinterpret_cast<float4*>(&b_[i]) =
                    *reinterpret_cast<const float4*>(&Bs[kk][tx * TN + i]);
            #pragma unroll
            for (int i = 0; i < TM; i++)
                #pragma unroll
                for (int j = 0; j < TN; j++)
                    acc[i][j] = fmaf(a_[i], b_[j], acc[i][j]);
        }
        __syncthreads();
    }

    float bb[TN];
    #pragma unroll
    for (int j = 0; j < TN; j++) bb[j] = bias ? bias[bn + tx * TN + j] : 0.f;

    #pragma unroll
    for (int i = 0; i < TM; i++) {
        int gm = bm + ty * TM + i;
        float outv[TN];
        #pragma unroll
        for (int j = 0; j < TN; j++) outv[j] = acc[i][j] + bb[j];
        #pragma unroll
        for (int j = 0; j < TN; j += 4)
            *reinterpret_cast<float4*>(&C[(size_t)gm * N + bn + tx * TN + j]) =
                *reinterpret_cast<const float4*>(&outv[j]);
    }
}

// ---------------- ControlUnit tail ----------------
__global__ void control_kernel(const float* __restrict__ cq, const float* __restrict__ cw,
                               const int* __restrict__ mask, const float* __restrict__ Wca,
                               const float* __restrict__ bca,
                               float* __restrict__ cv_out, float* __restrict__ cnew)
{
    int b = blockIdx.x, tid = threadIdx.x;   // 256 threads
    __shared__ float u[DIM];
    __shared__ float s[LW];
    __shared__ float red[8];
    for (int d = tid; d < DIM; d += 256) u[d] = cq[(size_t)b * DIM + d] * Wca[d];
    __syncthreads();
    const float* cwb = cw + (size_t)b * LW * DIM;
    for (int l = 0; l < LW; l++) {
        float p = 0.f;
        for (int d = tid; d < DIM; d += 256) p += u[d] * cwb[(size_t)l * DIM + d];
        float tot = blkSum<8>(p, red);
        if (tid == 0) s[l] = (mask[b * LW + l] > 0) ? (tot + bca[0]) : -INFINITY;
    }
    __syncthreads();
    if (tid == 0) {
        float mx = -INFINITY;
        for (int l = 0; l < LW; l++) mx = fmaxf(mx, s[l]);
        float sm = 0.f;
        for (int l = 0; l < LW; l++) { float e = __expf(s[l] - mx); s[l] = e; sm += e; }
        float inv = 1.f / sm;
        for (int l = 0; l < LW; l++) { s[l] *= inv; cv_out[b * LW + l] = s[l]; }
    }
    __syncthreads();
    for (int d = tid; d < DIM; d += 256) {
        float a = 0.f;
        for (int l = 0; l < LW; l++) a = fmaf(s[l], cwb[(size_t)l * DIM + d], a);
        cnew[(size_t)b * DIM + d] = a;
    }
}

// ---------------- softmax over channels v2: warp-per-pixel ----------
// 512 threads = 16 warps; rounds of 14 pixels on warps 0..13; smem-staged transposed rv write.
__global__ void __launch_bounds__(512) softmax_rv_kernel(
    const float* __restrict__ ra, const __nv_bfloat16* __restrict__ kT2,
    float* __restrict__ rv_out, float* __restrict__ r_out)
{
    const int b = blockIdx.x, tid = threadIdx.x;
    const int w = tid >> 5, lane = tid & 31;
    __shared__ float tile[14][516];
    __shared__ float rsum[DIM];
    const float* rab = ra + (size_t)b * PIX * DIM;
    const __nv_bfloat16* kb = kT2 + (size_t)b * PIX * 1024;
    float* rvb = rv_out + (size_t)b * DIM * PIX;

    if (tid < DIM) rsum[tid] = 0.f;
    float racc[16];
    #pragma unroll
    for (int j = 0; j < 16; j++) racc[j] = 0.f;
    __syncthreads();

    for (int pp = 0; pp < 14; pp++) {
        if (w < 14) {
            const int p = pp * 14 + w;
            float x[16];
            #pragma unroll
            for (int q = 0; q < 4; q++) {
                float4 v = *reinterpret_cast<const float4*>(rab + (size_t)p * DIM + q * 128 + lane * 4);
                x[q * 4 + 0] = v.x; x[q * 4 + 1] = v.y; x[q * 4 + 2] = v.z; x[q * 4 + 3] = v.w;
            }
            float mx = x[0];
            #pragma unroll
            for (int j = 1; j < 16; j++) mx = fmaxf(mx, x[j]);
            #pragma unroll
            for (int o = 16; o > 0; o >>= 1) mx = fmaxf(mx, __shfl_xor_sync(0xffffffffu, mx, o));
            float sm = 0.f;
            #pragma unroll
            for (int j = 0; j < 16; j++) { x[j] = __expf(x[j] - mx); sm += x[j]; }
            #pragma unroll
            for (int o = 16; o > 0; o >>= 1) sm += __shfl_xor_sync(0xffffffffu, sm, o);
            const float inv = 1.f / sm;
            #pragma unroll
            for (int q = 0; q < 4; q++) {
                float4 rv4;
                rv4.x = x[q * 4 + 0] * inv; rv4.y = x[q * 4 + 1] * inv;
                rv4.z = x[q * 4 + 2] * inv; rv4.w = x[q * 4 + 3] * inv;
                *reinterpret_cast<float4*>(&tile[w][q * 128 + lane * 4]) = rv4;
                // k hi/lo: 4 bf16 each = 8B
                const size_t kidx = (size_t)p * 1024 + q * 128 + lane * 4;
                __nv_bfloat162 kh0 = *reinterpret_cast<const __nv_bfloat162*>(kb + kidx);
                __nv_bfloat162 kh1 = *reinterpret_cast<const __nv_bfloat162*>(kb + kidx + 2);
                __nv_bfloat162 kl0 = *reinterpret_cast<const __nv_bfloat162*>(kb + kidx + 512);
                __nv_bfloat162 kl1 = *reinterpret_cast<const __nv_bfloat162*>(kb + kidx + 514);
                racc[q * 4 + 0] = fmaf(rv4.x, __bfloat162float(kh0.x) + __bfloat162float(kl0.x), racc[q * 4 + 0]);
                racc[q * 4 + 1] = fmaf(rv4.y, __bfloat162float(kh0.y) + __bfloat162float(kl0.y), racc[q * 4 + 1]);
                racc[q * 4 + 2] = fmaf(rv4.z, __bfloat162float(kh1.x) + __bfloat162float(kl1.x), racc[q * 4 + 2]);
                racc[q * 4 + 3] = fmaf(rv4.w, __bfloat162float(kh1.y) + __bfloat162float(kl1.y), racc[q * 4 + 3]);
            }
        }
        __syncthreads();
        // transposed write: warp w covers channels [w*32, w*32+32)
        #pragma unroll 1
        for (int cc = 0; cc < 32; cc++) {
            int c = w * 32 + cc;
            if (lane < 14) rvb[(size_t)c * PIX + pp * 14 + lane] = tile[lane][c];
        }
        __syncthreads();
    }

    // reduce racc across warps (channels q*128 + lane*4 + j)
    #pragma unroll
    for (int q = 0; q < 4; q++)
        #pragma unroll
        for (int j = 0; j < 4; j++)
            atomicAdd(&rsum[q * 128 + lane * 4 + j], racc[q * 4 + j]);
    __syncthreads();
    if (tid < DIM) r_out[(size_t)b * DIM + tid] = rsum[tid];
}

// ---------------- gate, sa softmax over T, m_sa ----------------
__global__ void gate_sa_kernel(const float* __restrict__ cnew, const float* __restrict__ Wc,
                               const float* __restrict__ bc,   const float* __restrict__ cs,
                               const float* __restrict__ Wsa,  const float* __restrict__ bsa,
                               const float* __restrict__ ms,
                               float* __restrict__ gate_out, float* __restrict__ msa_out)
{
    int b = blockIdx.x, tid = threadIdx.x;   // 256 threads
    __shared__ float red[8];
    __shared__ float sa[TT];
    __shared__ float gsh;
    float p = 0.f;
    for (int d = tid; d < DIM; d += 256) p += cnew[(size_t)b * DIM + d] * Wc[d];
    float tot = blkSum<8>(p, red);
    if (tid == 0) gsh = 1.f / (1.f + __expf(-(tot + bc[0])));
    __syncthreads();
    float gate = gsh;
    for (int t8 = 0; t8 < TT; t8++) {
        float qv = 0.f;
        const float* csrow = cs + ((size_t)t8 * BATCH + b) * DIM;
        for (int d = tid; d < DIM; d += 256) qv += csrow[d] * Wsa[d];
        float qt = blkSum<8>(qv, red);
        if (tid == 0) sa[t8] = gate * qt + bsa[0];
    }
    __syncthreads();
    if (tid == 0) {
        float mx = -INFINITY;
        for (int i = 0; i < TT; i++) mx = fmaxf(mx, sa[i]);
        float sm = 0.f;
        for (int i = 0; i < TT; i++) { float e = __expf(sa[i] - mx); sa[i] = e; sm += e; }
        float inv = 1.f / sm;
        for (int i = 0; i < TT; i++) sa[i] *= inv;
    }
    __syncthreads();
    for (int d = tid; d < DIM; d += 256) {
        float a = 0.f;
        #pragma unroll
        for (int i = 0; i < TT; i++)
            a = fmaf(sa[i], ms[((size_t)i * BATCH + b) * DIM + d], a);
        msa_out[(size_t)b * DIM + d] = a;
    }
    if (tid == 0) gate_out[b] = gate;
}

// ---------------- final ----------------
__global__ void final_kernel(const float* __restrict__ m, const float* __restrict__ mm,
                             const float* __restrict__ tmp, const float* __restrict__ gate,
                             float* __restrict__ mnew)
{
    int i = blockIdx.x * 256 + threadIdx.x;
    int b = i >> 9;
    float g = gate[b];
    mnew[i] = g * m[i] + (1.f - g) * (mm[i] + tmp[i]);
}

// ---------------- launch ----------------
extern "C" void kernel_launch(void* const* d_in, const int* in_sizes, int n_in,
                              void* d_out, int out_size)
{
    const float* c    = (const float*)d_in[0];
    const float* m    = (const float*)d_in[1];
    const float* k    = (const float*)d_in[2];
    const float* q    = (const float*)d_in[3];
    const float* cw   = (const float*)d_in[4];
    const int*   mask = (const int*)  d_in[5];
    const float* cs   = (const float*)d_in[6];
    const float* ms   = (const float*)d_in[7];
    const float* Wcq  = (const float*)d_in[8];
    const float* bcq  = (const float*)d_in[9];
    const float* Wca  = (const float*)d_in[10];
    const float* bca  = (const float*)d_in[11];
    const float* Wm_r = (const float*)d_in[12];
    const float* bm_r = (const float*)d_in[13];
    const float* Wk   = (const float*)d_in[14];
    const float* bk   = (const float*)d_in[15];
    const float* WI   = (const float*)d_in[16];
    const float* bI   = (const float*)d_in[17];
    const float* Wra  = (const float*)d_in[18];
    const float* bra  = (const float*)d_in[19];
    const float* Wm_w = (const float*)d_in[20];
    const float* bm_w = (const float*)d_in[21];
    const float* Wsa  = (const float*)d_in[22];
    const float* bsa  = (const float*)d_in[23];
    const float* Wm2  = (const float*)d_in[24];
    const float* bm2  = (const float*)d_in[25];
    const float* Wc   = (const float*)d_in[26];
    const float* bc   = (const float*)d_in[27];
    const float* Ws   = (const float*)d_in[28];

    float* out      = (float*)d_out;
    float* out_cnew = out;                       // [B,D]
    float* out_mnew = out + 131072;              // [B,D]
    float* out_cv   = out + 262144;              // [B,L]
    float* out_rv   = out + 270336;              // [B,D,H,W]

    __nv_bfloat16 *p_kT2, *p_I2, *p_J2, *p_Wk2, *p_WI2, *p_Wra2;
    float *p_ra, *p_cq, *p_mI, *p_r, *p_mprev, *p_mm, *p_msa, *p_tmp, *p_gate;
    cudaGetSymbolAddress((void**)&p_kT2,  g_kT2);
    cudaGetSymbolAddress((void**)&p_I2,   g_I2);
    cudaGetSymbolAddress((void**)&p_J2,   g_J2);
    cudaGetSymbolAddress((void**)&p_Wk2,  g_Wk2);
    cudaGetSymbolAddress((void**)&p_WI2,  g_WI2);
    cudaGetSymbolAddress((void**)&p_Wra2, g_Wra2);
    cudaGetSymbolAddress((void**)&p_ra,   g_ra);
    cudaGetSymbolAddress((void**)&p_cq,   g_cq);
    cudaGetSymbolAddress((void**)&p_mI,   g_mI);
    cudaGetSymbolAddress((void**)&p_r,    g_r);
    cudaGetSymbolAddress((void**)&p_mprev,g_mprev);
    cudaGetSymbolAddress((void**)&p_mm,   g_mm);
    cudaGetSymbolAddress((void**)&p_msa,  g_msa);
    cudaGetSymbolAddress((void**)&p_tmp,  g_tmp);
    cudaGetSymbolAddress((void**)&p_gate, g_gate);

    cudaFuncSetAttribute(mma_gemm<512,  false, 0>, cudaFuncAttributeMaxDynamicSharedMemorySize, MG_SMEM);
    cudaFuncSetAttribute(mma_gemm<1024, true,  0>, cudaFuncAttributeMaxDynamicSharedMemorySize, MG_SMEM);
    cudaFuncSetAttribute(mma_gemm<512,  false, 1>, cudaFuncAttributeMaxDynamicSharedMemorySize, MG_SMEM);

    // 0. conversions: weights hi/lo; k -> kT hi/lo
    split_w_kernel<<<(DIM*DIM + 255)/256, 256>>>(Wk,  p_Wk2,  DIM, DIM);
    split_w_kernel<<<(DIM*2*DIM + 255)/256, 256>>>(WI, p_WI2, DIM, 2*DIM);
    split_w_kernel<<<(DIM*DIM + 255)/256, 256>>>(Wra, p_Wra2, DIM, DIM);
    transpose_split_k<<<dim3(7, 16, BATCH), dim3(32, 8)>>>(k, p_kT2);

    // 1. cq = [c|q] @ Wcq^T + bcq
    gemm_nt<64, 64, 16, 4, 4, true><<<dim3(8, 4), 256>>>(
        c, q, Wcq, bcq, nullptr, p_cq, BATCH, DIM, 2 * DIM, 1);

    // 2. ControlUnit tail -> cv, c_new
    control_kernel<<<BATCH, 256>>>(p_cq, cw, mask, Wca, bca, out_cv, out_cnew);

    // 3. mI = m @ Wm_r^T + bm_r
    gemm_nt<64, 64, 16, 4, 4, false><<<dim3(8, 4), 256>>>(
        m, nullptr, Wm_r, bm_r, nullptr, p_mI, BATCH, DIM, DIM, 1);

    // 4. I = mI ⊙ (kT @ Wk^T + bk) -> hi/lo          [HMMA]
    mma_gemm<512, false, 0><<<dim3(4, 392), 256, MG_SMEM>>>(
        p_kT2, nullptr, p_Wk2, bk, p_mI, p_I2, nullptr);

    // 5. J = c_new ⊙ ([I|kT] @ WI^T + bI) -> hi/lo   [HMMA]
    mma_gemm<1024, true, 0><<<dim3(4, 392), 256, MG_SMEM>>>(
        p_I2, p_kT2, p_WI2, bI, out_cnew, p_J2, nullptr);

    // 6. ra = J @ Wra^T + bra -> fp32                [HMMA]
    mma_gemm<512, false, 1><<<dim3(4, 392), 256, MG_SMEM>>>(
        p_J2, nullptr, p_Wra2, bra, nullptr, nullptr, p_ra);

    // 7. rv = softmax_c(ra) -> d_out (transposed), r = sum_p rv*k
    softmax_rv_kernel<<<BATCH, 512>>>(p_ra, p_kT2, out_rv, p_r);

    // 8. m_prev = [r|m] @ Wm_w^T + bm_w
    gemm_nt<64, 64, 16, 4, 4, true><<<dim3(8, 4), 256>>>(
        p_r, m, Wm_w, bm_w, nullptr, p_mprev, BATCH, DIM, 2 * DIM, 1);

    // 9. m_ = m_prev @ Wm2^T + bm2
    gemm_nt<64, 64, 16, 4, 4, false><<<dim3(8, 4), 256>>>(
        p_mprev, nullptr, Wm2, bm2, nullptr, p_mm, BATCH, DIM, DIM, 1);

    // 10. gate, sa softmax, m_sa
    gate_sa_kernel<<<BATCH, 256>>>(out_cnew, Wc, bc, cs, Wsa, bsa, ms, p_gate, p_msa);

    // 11. tmp = m_sa @ Ws^T
    gemm_nt<64, 64, 16, 4, 4, false><<<dim3(8, 4), 256>>>(
        p_msa, nullptr, Ws, nullptr, nullptr, p_tmp, BATCH, DIM, DIM, 1);

    // 12. m_new = gate*m + (1-gate)*(m_ + tmp)
    final_kernel<<<(BATCH * DIM) / 256, 256>>>(m, p_mm, p_tmp, p_gate, out_mnew);
}

// round 5
// speedup vs baseline: 2.8933x; 1.0547x over previous
#include <cuda_runtime.h>
#include <cuda_bf16.h>
#include <math.h>
#include <stdint.h>

#define BATCH 256
#define DIM   512
#define LW    32
#define PIX   196
#define TT    8
#define MBIG  (BATCH*PIX)   // 50176

// ---------------- scratch (static __device__ — allocation-guard safe) ----------------
// hi/lo packed layout: [rows][2][512]  (hi at +0, lo at +512), row stride 1024
__device__ __nv_bfloat16 g_kT2[MBIG*1024];
__device__ __nv_bfloat16 g_I2 [MBIG*1024];
__device__ __nv_bfloat16 g_J2 [MBIG*1024];
__device__ float g_ra  [MBIG*DIM];
__device__ __nv_bfloat16 g_Wk2 [DIM*1024];   // [N][2][512]
__device__ __nv_bfloat16 g_WI2 [DIM*2048];   // [N][2][1024]
__device__ __nv_bfloat16 g_Wra2[DIM*1024];
__device__ float g_cq  [BATCH*DIM];
__device__ float g_mI  [BATCH*DIM];
__device__ float g_r   [BATCH*DIM];
__device__ float g_mprev[BATCH*DIM];
__device__ float g_mm  [BATCH*DIM];
__device__ float g_msa [BATCH*DIM];
__device__ float g_tmp [BATCH*DIM];
__device__ float g_gate[BATCH];

// ================= helpers =================
__device__ __forceinline__ uint32_t smem_u32(const void* p) {
    uint32_t a;
    asm("{ .reg .u64 t; cvta.to.shared.u64 t, %1; cvt.u32.u64 %0, t; }" : "=r"(a) : "l"(p));
    return a;
}
__device__ __forceinline__ void cpasync16(uint32_t dst, const void* src) {
    asm volatile("cp.async.cg.shared.global [%0], [%1], 16;" :: "r"(dst), "l"(src) : "memory");
}
__device__ __forceinline__ void cp_commit() { asm volatile("cp.async.commit_group;" ::: "memory"); }
__device__ __forceinline__ void cp_wait1() { asm volatile("cp.async.wait_group 1;" ::: "memory"); }
__device__ __forceinline__ void cp_wait0() { asm volatile("cp.async.wait_group 0;" ::: "memory"); }

__device__ __forceinline__ void ldm_x4(uint32_t& r0, uint32_t& r1, uint32_t& r2, uint32_t& r3, uint32_t a) {
    asm volatile("ldmatrix.sync.aligned.m8n8.x4.shared.b16 {%0,%1,%2,%3}, [%4];"
                 : "=r"(r0), "=r"(r1), "=r"(r2), "=r"(r3) : "r"(a));
}
__device__ __forceinline__ void ldm_x2(uint32_t& r0, uint32_t& r1, uint32_t a) {
    asm volatile("ldmatrix.sync.aligned.m8n8.x2.shared.b16 {%0,%1}, [%2];"
                 : "=r"(r0), "=r"(r1) : "r"(a));
}
__device__ __forceinline__ void mma16816(float* c, const uint32_t* a, const uint32_t* b) {
    asm volatile("mma.sync.aligned.m16n8k16.row.col.f32.bf16.bf16.f32 "
                 "{%0,%1,%2,%3}, {%4,%5,%6,%7}, {%8,%9}, {%0,%1,%2,%3};"
                 : "+f"(c[0]), "+f"(c[1]), "+f"(c[2]), "+f"(c[3])
                 : "r"(a[0]), "r"(a[1]), "r"(a[2]), "r"(a[3]), "r"(b[0]), "r"(b[1]));
}

// ================= HMMA bf16-split GEMM =================
// Per K-step loads Ah,Al,Bh,Bl tiles once; issues 3 combos (AhBh + AhBl + AlBh).
// 3-stage cp.async ring, 32KB/stage, wait_group 1.
#define MG_SMEM (3*32768)

template<int K, bool CONCAT, int EPI>
__global__ void __launch_bounds__(256) mma_gemm(
    const __nv_bfloat16* __restrict__ A0, const __nv_bfloat16* __restrict__ A1,
    const __nv_bfloat16* __restrict__ W,
    const float* __restrict__ bias, const float* __restrict__ scale,
    __nv_bfloat16* __restrict__ O, float* __restrict__ Of)
{
    constexpr int KIT = K / 32;
    extern __shared__ __align__(128) char dsm[];
    const uint32_t smb = smem_u32(dsm);

    const int tid = threadIdx.x, lane = tid & 31, wid = tid >> 5;
    const int bm = blockIdx.y * 128, bn = blockIdx.x * 128;
    const int wm = (wid >> 2) * 64, wn = (wid & 3) * 32;

    float acc[4][4][4];
    #pragma unroll
    for (int i = 0; i < 4; i++)
        #pragma unroll
        for (int j = 0; j < 4; j++)
            #pragma unroll
            for (int v = 0; v < 4; v++) acc[i][j][v] = 0.f;

    auto load_stage = [&](int it, int stage) {
        uint32_t sb = smb + (uint32_t)stage * 32768u;
        int k0 = it * 32;
        const __nv_bfloat16* Asrc = A0;
        int ac = k0;
        if (CONCAT && k0 >= 512) { Asrc = A1; ac = k0 - 512; }
        const int cc = tid & 3;
        #pragma unroll
        for (int j = 0; j < 2; j++) {
            int row = (tid >> 2) + j * 64;
            uint32_t d = sb + row * 64 + ((cc * 16) ^ (((row >> 1) & 3) << 4));
            const __nv_bfloat16* ga = Asrc + (size_t)(bm + row) * 1024 + ac + cc * 8;
            cpasync16(d,          ga);          // A_hi
            cpasync16(d + 8192u,  ga + 512);    // A_lo
            const __nv_bfloat16* gw = W + (size_t)(bn + row) * (2 * K) + k0 + cc * 8;
            cpasync16(d + 16384u, gw);          // B_hi
            cpasync16(d + 24576u, gw + K);      // B_lo
        }
    };

    load_stage(0, 0); cp_commit();
    if (KIT > 1) { load_stage(1, 1); cp_commit(); }

    for (int it = 0; it < KIT; ++it) {
        if (it + 1 < KIT) cp_wait1(); else cp_wait0();
        __syncthreads();
        if (it + 2 < KIT) { load_stage(it + 2, (it + 2) % 3); cp_commit(); }

        uint32_t sb  = smb + (uint32_t)(it % 3) * 32768u;
        uint32_t sAh = sb, sAl = sb + 8192u, sBh = sb + 16384u, sBl = sb + 24576u;
        #pragma unroll
        for (int kp = 0; kp < 2; kp++) {
            uint32_t ah[4][4], al[4][4], bh[4][2], bl[4][2];
            #pragma unroll
            for (int mi = 0; mi < 4; mi++) {
                int row = wm + mi * 16 + (lane & 15);
                int chunk = (kp * 2 + (lane >> 4)) ^ ((row >> 1) & 3);
                uint32_t off = row * 64 + chunk * 16;
                ldm_x4(ah[mi][0], ah[mi][1], ah[mi][2], ah[mi][3], sAh + off);
                ldm_x4(al[mi][0], al[mi][1], al[mi][2], al[mi][3], sAl + off);
            }
            #pragma unroll
            for (int ni = 0; ni < 4; ni++) {
                int l = lane & 15;
                int nrow = wn + ni * 8 + (l & 7);
                int chunk = (kp * 2 + (l >> 3)) ^ ((nrow >> 1) & 3);
                uint32_t off = nrow * 64 + chunk * 16;
                ldm_x2(bh[ni][0], bh[ni][1], sBh + off);
                ldm_x2(bl[ni][0], bl[ni][1], sBl + off);
            }
            #pragma unroll
            for (int mi = 0; mi < 4; mi++)
                #pragma unroll
                for (int ni = 0; ni < 4; ni++)
                    mma16816(acc[mi][ni], ah[mi], bh[ni]);
            #pragma unroll
            for (int mi = 0; mi < 4; mi++)
                #pragma unroll
                for (int ni = 0; ni < 4; ni++)
                    mma16816(acc[mi][ni], ah[mi], bl[ni]);
            #pragma unroll
            for (int mi = 0; mi < 4; mi++)
                #pragma unroll
                for (int ni = 0; ni < 4; ni++)
                    mma16816(acc[mi][ni], al[mi], bh[ni]);
        }
        __syncthreads();
    }

    // ---------------- epilogue ----------------
    #pragma unroll
    for (int ni = 0; ni < 4; ni++) {
        const int n0 = bn + wn + ni * 8 + 2 * (lane & 3);
        const float b0 = bias[n0], b1 = bias[n0 + 1];
        #pragma unroll
        for (int mi = 0; mi < 4; mi++) {
            const int r0 = bm + wm + mi * 16 + (lane >> 2);
            const int r1 = r0 + 8;
            float* c = acc[mi][ni];
            if (EPI == 0) {
                const float* s0 = scale + (size_t)(r0 / PIX) * DIM;
                const float* s1 = scale + (size_t)(r1 / PIX) * DIM;
                float v00 = (c[0] + b0) * s0[n0], v01 = (c[1] + b1) * s0[n0 + 1];
                float v10 = (c[2] + b0) * s1[n0], v11 = (c[3] + b1) * s1[n0 + 1];
                __nv_bfloat16 h00 = __float2bfloat16(v00), h01 = __float2bfloat16(v01);
                __nv_bfloat16 h10 = __float2bfloat16(v10), h11 = __float2bfloat16(v11);
                uint32_t hi0 = (uint32_t)__bfloat16_as_ushort(h00) | ((uint32_t)__bfloat16_as_ushort(h01) << 16);
                uint32_t hi1 = (uint32_t)__bfloat16_as_ushort(h10) | ((uint32_t)__bfloat16_as_ushort(h11) << 16);
                __nv_bfloat16 l00 = __float2bfloat16(v00 - __bfloat162float(h00));
                __nv_bfloat16 l01 = __float2bfloat16(v01 - __bfloat162float(h01));
                __nv_bfloat16 l10 = __float2bfloat16(v10 - __bfloat162float(h10));
                __nv_bfloat16 l11 = __float2bfloat16(v11 - __bfloat162float(h11));
                uint32_t lo0 = (uint32_t)__bfloat16_as_ushort(l00) | ((uint32_t)__bfloat16_as_ushort(l01) << 16);
                uint32_t lo1 = (uint32_t)__bfloat16_as_ushort(l10) | ((uint32_t)__bfloat16_as_ushort(l11) << 16);
                *reinterpret_cast<uint32_t*>(O + (size_t)r0 * 1024 + n0)       = hi0;
                *reinterpret_cast<uint32_t*>(O + (size_t)r0 * 1024 + 512 + n0) = lo0;
                *reinterpret_cast<uint32_t*>(O + (size_t)r1 * 1024 + n0)       = hi1;
                *reinterpret_cast<uint32_t*>(O + (size_t)r1 * 1024 + 512 + n0) = lo1;
            } else {
                float2 v0 = make_float2(c[0] + b0, c[1] + b1);
                float2 v1 = make_float2(c[2] + b0, c[3] + b1);
                *reinterpret_cast<float2*>(Of + (size_t)r0 * DIM + n0) = v0;
                *reinterpret_cast<float2*>(Of + (size_t)r1 * DIM + n0) = v1;
            }
        }
    }
}

// ================= small fp32 GEMM: register-prefetch double-buffered =================
// C[M x 512] = A[M x K] @ W[512 x K]^T + bias ;  BM=BN=64, BK=32, 256 thr, TM=TN=4
template<int K, bool CONCAT>
__global__ void __launch_bounds__(256) gemm_small(
    const float* __restrict__ A0, const float* __restrict__ A1,
    const float* __restrict__ W, const float* __restrict__ bias,
    float* __restrict__ C)
{
    constexpr int BM = 64, BN = 64, BK = 32;
    constexpr int NIT = K / BK;
    constexpr int halfK = K / 2;
    __shared__ __align__(16) float As[2][BK][BM];
    __shared__ __align__(16) float Bs[2][BK][BN];

    const int tid = threadIdx.x;
    const int bm = blockIdx.y * BM, bn = blockIdx.x * BN;
    const int tx = tid & 15, ty = tid >> 4;

    float4 pa[2], pb[2];
    auto gload = [&](int it) {
        int k0 = it * BK;
        #pragma unroll
        for (int j = 0; j < 2; j++) {
            int f = tid + j * 256;
            int r = f >> 3, c4 = (f & 7) * 4;
            int gk = k0 + c4;
            const float* srcA;
            if (CONCAT) {
                srcA = (gk < halfK) ? (A0 + (size_t)(bm + r) * halfK + gk)
                                    : (A1 + (size_t)(bm + r) * halfK + (gk - halfK));
            } else {
                srcA = A0 + (size_t)(bm + r) * K + gk;
            }
            pa[j] = *reinterpret_cast<const float4*>(srcA);
            pb[j] = *reinterpret_cast<const float4*>(W + (size_t)(bn + r) * K + gk);
        }
    };
    auto sstore = [&](int buf) {
        #pragma unroll
        for (int j = 0; j < 2; j++) {
            int f = tid + j * 256;
            int r = f >> 3, c4 = (f & 7) * 4;
            As[buf][c4 + 0][r] = pa[j].x; As[buf][c4 + 1][r] = pa[j].y;
            As[buf][c4 + 2][r] = pa[j].z; As[buf][c4 + 3][r] = pa[j].w;
            Bs[buf][c4 + 0][r] = pb[j].x; Bs[buf][c4 + 1][r] = pb[j].y;
            Bs[buf][c4 + 2][r] = pb[j].z; Bs[buf][c4 + 3][r] = pb[j].w;
        }
    };

    float acc[4][4];
    #pragma unroll
    for (int i = 0; i < 4; i++)
        #pragma unroll
        for (int j = 0; j < 4; j++) acc[i][j] = 0.f;

    gload(0); sstore(0); __syncthreads();
    for (int it = 0; it < NIT; ++it) {
        if (it + 1 < NIT) gload(it + 1);
        const int buf = it & 1;
        #pragma unroll
        for (int kk = 0; kk < BK; kk++) {
            float4 a = *reinterpret_cast<const float4*>(&As[buf][kk][ty * 4]);
            float4 b = *reinterpret_cast<const float4*>(&Bs[buf][kk][tx * 4]);
            acc[0][0] = fmaf(a.x, b.x, acc[0][0]); acc[0][1] = fmaf(a.x, b.y, acc[0][1]);
            acc[0][2] = fmaf(a.x, b.z, acc[0][2]); acc[0][3] = fmaf(a.x, b.w, acc[0][3]);
            acc[1][0] = fmaf(a.y, b.x, acc[1][0]); acc[1][1] = fmaf(a.y, b.y, acc[1][1]);
            acc[1][2] = fmaf(a.y, b.z, acc[1][2]); acc[1][3] = fmaf(a.y, b.w, acc[1][3]);
            acc[2][0] = fmaf(a.z, b.x, acc[2][0]); acc[2][1] = fmaf(a.z, b.y, acc[2][1]);
            acc[2][2] = fmaf(a.z, b.z, acc[2][2]); acc[2][3] = fmaf(a.z, b.w, acc[2][3]);
            acc[3][0] = fmaf(a.w, b.x, acc[3][0]); acc[3][1] = fmaf(a.w, b.y, acc[3][1]);
            acc[3][2] = fmaf(a.w, b.z, acc[3][2]); acc[3][3] = fmaf(a.w, b.w, acc[3][3]);
        }
        __syncthreads();
        if (it + 1 < NIT) { sstore((it + 1) & 1); __syncthreads(); }
    }

    float bb[4];
    #pragma unroll
    for (int j = 0; j < 4; j++) bb[j] = bias ? bias[bn + tx * 4 + j] : 0.f;
    #pragma unroll
    for (int i = 0; i < 4; i++) {
        int gm = bm + ty * 4 + i;
        float4 v = make_float4(acc[i][0] + bb[0], acc[i][1] + bb[1],
                               acc[i][2] + bb[2], acc[i][3] + bb[3]);
        *reinterpret_cast<float4*>(&C[(size_t)gm * DIM + bn + tx * 4]) = v;
    }
}

// ================= conversions =================
__global__ void split_w_kernel(const float* __restrict__ w, __nv_bfloat16* __restrict__ o, int N, int K)
{
    int i = blockIdx.x * 256 + threadIdx.x;
    if (i < N * K) {
        int n = i / K, k = i % K;
        float v = w[i];
        __nv_bfloat16 h = __float2bfloat16(v);
        o[(size_t)n * 2 * K + k]     = h;
        o[(size_t)n * 2 * K + K + k] = __float2bfloat16(v - __bfloat162float(h));
    }
}

// k [B,D,P] -> kT2 [B*P][2][512] hi/lo
__global__ void transpose_split_k(const float* __restrict__ k, __nv_bfloat16* __restrict__ kT2)
{
    __shared__ float tile[32][33];
    int b  = blockIdx.z;
    int p0 = blockIdx.x * 32;
    int c0 = blockIdx.y * 32;
    int tx = threadIdx.x, ty = threadIdx.y;
    #pragma unroll
    for (int j = 0; j < 32; j += 8) {
        int c = c0 + ty + j, p = p0 + tx;
        if (p < PIX) tile[ty + j][tx] = k[((size_t)b * DIM + c) * PIX + p];
    }
    __syncthreads();
    #pragma unroll
    for (int j = 0; j < 32; j += 8) {
        int p = p0 + ty + j, c = c0 + tx;
        if (p < PIX) {
            float v = tile[tx][ty + j];
            __nv_bfloat16 h = __float2bfloat16(v);
            size_t o = ((size_t)b * PIX + p) * 1024 + c;
            kT2[o]       = h;
            kT2[o + 512] = __float2bfloat16(v - __bfloat162float(h));
        }
    }
}

// ---------------- reduction helpers ----------------
template<int NW>
__device__ __forceinline__ float blkSum(float v, float* red) {
    #pragma unroll
    for (int o = 16; o > 0; o >>= 1) v += __shfl_xor_sync(0xffffffffu, v, o);
    __syncthreads();
    if ((threadIdx.x & 31) == 0) red[threadIdx.x >> 5] = v;
    __syncthreads();
    float s = 0.f;
    #pragma unroll
    for (int i = 0; i < NW; i++) s += red[i];
    return s;
}

// ---------------- ControlUnit tail ----------------
__global__ void control_kernel(const float* __restrict__ cq, const float* __restrict__ cw,
                               const int* __restrict__ mask, const float* __restrict__ Wca,
                               const float* __restrict__ bca,
                               float* __restrict__ cv_out, float* __restrict__ cnew)
{
    int b = blockIdx.x, tid = threadIdx.x;   // 256 threads
    __shared__ float u[DIM];
    __shared__ float s[LW];
    __shared__ float red[8];
    for (int d = tid; d < DIM; d += 256) u[d] = cq[(size_t)b * DIM + d] * Wca[d];
    __syncthreads();
    const float* cwb = cw + (size_t)b * LW * DIM;
    for (int l = 0; l < LW; l++) {
        float p = 0.f;
        for (int d = tid; d < DIM; d += 256) p += u[d] * cwb[(size_t)l * DIM + d];
        float tot = blkSum<8>(p, red);
        if (tid == 0) s[l] = (mask[b * LW + l] > 0) ? (tot + bca[0]) : -INFINITY;
    }
    __syncthreads();
    if (tid == 0) {
        float mx = -INFINITY;
        for (int l = 0; l < LW; l++) mx = fmaxf(mx, s[l]);
        float sm = 0.f;
        for (int l = 0; l < LW; l++) { float e = __expf(s[l] - mx); s[l] = e; sm += e; }
        float inv = 1.f / sm;
        for (int l = 0; l < LW; l++) { s[l] *= inv; cv_out[b * LW + l] = s[l]; }
    }
    __syncthreads();
    for (int d = tid; d < DIM; d += 256) {
        float a = 0.f;
        for (int l = 0; l < LW; l++) a = fmaf(s[l], cwb[(size_t)l * DIM + d], a);
        cnew[(size_t)b * DIM + d] = a;
    }
}

// ---------------- softmax over channels v3: warp-per-pixel, 28-pixel write staging ----------
#define SMRV_TILE_STRIDE 517
#define SMRV_SMEM (28*SMRV_TILE_STRIDE*4)

__global__ void __launch_bounds__(512) softmax_rv_kernel(
    const float* __restrict__ ra, const __nv_bfloat16* __restrict__ kT2,
    float* __restrict__ rv_out, float* __restrict__ r_out)
{
    extern __shared__ float tile[];          // [28][517]
    __shared__ float rsum[DIM];
    const int b = blockIdx.x, tid = threadIdx.x;
    const int w = tid >> 5, lane = tid & 31;
    const float* rab = ra + (size_t)b * PIX * DIM;
    const __nv_bfloat16* kb = kT2 + (size_t)b * PIX * 1024;
    float* rvb = rv_out + (size_t)b * DIM * PIX;

    if (tid < DIM) rsum[tid] = 0.f;
    float racc[16];
    #pragma unroll
    for (int j = 0; j < 16; j++) racc[j] = 0.f;
    __syncthreads();

    for (int pp = 0; pp < 7; pp++) {
        if (w < 14) {
            #pragma unroll
            for (int half = 0; half < 2; half++) {
                const int i = half * 14 + w;
                const int p = pp * 28 + i;
                float x[16];
                #pragma unroll
                for (int q = 0; q < 4; q++) {
                    float4 v = *reinterpret_cast<const float4*>(rab + (size_t)p * DIM + q * 128 + lane * 4);
                    x[q * 4 + 0] = v.x; x[q * 4 + 1] = v.y; x[q * 4 + 2] = v.z; x[q * 4 + 3] = v.w;
                }
                float mx = x[0];
                #pragma unroll
                for (int j = 1; j < 16; j++) mx = fmaxf(mx, x[j]);
                #pragma unroll
                for (int o = 16; o > 0; o >>= 1) mx = fmaxf(mx, __shfl_xor_sync(0xffffffffu, mx, o));
                float sm = 0.f;
                #pragma unroll
                for (int j = 0; j < 16; j++) { x[j] = __expf(x[j] - mx); sm += x[j]; }
                #pragma unroll
                for (int o = 16; o > 0; o >>= 1) sm += __shfl_xor_sync(0xffffffffu, sm, o);
                const float inv = 1.f / sm;
                #pragma unroll
                for (int q = 0; q < 4; q++) {
                    float rv0 = x[q * 4 + 0] * inv, rv1 = x[q * 4 + 1] * inv;
                    float rv2 = x[q * 4 + 2] * inv, rv3 = x[q * 4 + 3] * inv;
                    float* tr = &tile[i * SMRV_TILE_STRIDE + q * 128 + lane * 4];
                    tr[0] = rv0; tr[1] = rv1; tr[2] = rv2; tr[3] = rv3;
                    const size_t kidx = (size_t)p * 1024 + q * 128 + lane * 4;
                    __nv_bfloat162 kh0 = *reinterpret_cast<const __nv_bfloat162*>(kb + kidx);
                    __nv_bfloat162 kh1 = *reinterpret_cast<const __nv_bfloat162*>(kb + kidx + 2);
                    __nv_bfloat162 kl0 = *reinterpret_cast<const __nv_bfloat162*>(kb + kidx + 512);
                    __nv_bfloat162 kl1 = *reinterpret_cast<const __nv_bfloat162*>(kb + kidx + 514);
                    racc[q * 4 + 0] = fmaf(rv0, __bfloat162float(kh0.x) + __bfloat162float(kl0.x), racc[q * 4 + 0]);
                    racc[q * 4 + 1] = fmaf(rv1, __bfloat162float(kh0.y) + __bfloat162float(kl0.y), racc[q * 4 + 1]);
                    racc[q * 4 + 2] = fmaf(rv2, __bfloat162float(kh1.x) + __bfloat162float(kl1.x), racc[q * 4 + 2]);
                    racc[q * 4 + 3] = fmaf(rv3, __bfloat162float(kh1.y) + __bfloat162float(kl1.y), racc[q * 4 + 3]);
                }
            }
        }
        __syncthreads();
        // transposed write: warp w covers channels [w*32, w*32+32); 112B contiguous per channel
        #pragma unroll 1
        for (int cc = 0; cc < 32; cc++) {
            int c = w * 32 + cc;
            if (lane < 28) rvb[(size_t)c * PIX + pp * 28 + lane] = tile[lane * SMRV_TILE_STRIDE + c];
        }
        __syncthreads();
    }

    #pragma unroll
    for (int q = 0; q < 4; q++)
        #pragma unroll
        for (int j = 0; j < 4; j++)
            atomicAdd(&rsum[q * 128 + lane * 4 + j], racc[q * 4 + j]);
    __syncthreads();
    if (tid < DIM) r_out[(size_t)b * DIM + tid] = rsum[tid];
}

// ---------------- gate, sa softmax over T, m_sa ----------------
__global__ void gate_sa_kernel(const float* __restrict__ cnew, const float* __restrict__ Wc,
                               const float* __restrict__ bc,   const float* __restrict__ cs,
                               const float* __restrict__ Wsa,  const float* __restrict__ bsa,
                               const float* __restrict__ ms,
                               float* __restrict__ gate_out, float* __restrict__ msa_out)
{
    int b = blockIdx.x, tid = threadIdx.x;   // 256 threads
    __shared__ float red[8];
    __shared__ float sa[TT];
    __shared__ float gsh;
    float p = 0.f;
    for (int d = tid; d < DIM; d += 256) p += cnew[(size_t)b * DIM + d] * Wc[d];
    float tot = blkSum<8>(p, red);
    if (tid == 0) gsh = 1.f / (1.f + __expf(-(tot + bc[0])));
    __syncthreads();
    float gate = gsh;
    for (int t8 = 0; t8 < TT; t8++) {
        float qv = 0.f;
        const float* csrow = cs + ((size_t)t8 * BATCH + b) * DIM;
        for (int d = tid; d < DIM; d += 256) qv += csrow[d] * Wsa[d];
        float qt = blkSum<8>(qv, red);
        if (tid == 0) sa[t8] = gate * qt + bsa[0];
    }
    __syncthreads();
    if (tid == 0) {
        float mx = -INFINITY;
        for (int i = 0; i < TT; i++) mx = fmaxf(mx, sa[i]);
        float sm = 0.f;
        for (int i = 0; i < TT; i++) { float e = __expf(sa[i] - mx); sa[i] = e; sm += e; }
        float inv = 1.f / sm;
        for (int i = 0; i < TT; i++) sa[i] *= inv;
    }
    __syncthreads();
    for (int d = tid; d < DIM; d += 256) {
        float a = 0.f;
        #pragma unroll
        for (int i = 0; i < TT; i++)
            a = fmaf(sa[i], ms[((size_t)i * BATCH + b) * DIM + d], a);
        msa_out[(size_t)b * DIM + d] = a;
    }
    if (tid == 0) gate_out[b] = gate;
}

// ---------------- final ----------------
__global__ void final_kernel(const float* __restrict__ m, const float* __restrict__ mm,
                             const float* __restrict__ tmp, const float* __restrict__ gate,
                             float* __restrict__ mnew)
{
    int i = blockIdx.x * 256 + threadIdx.x;
    int b = i >> 9;
    float g = gate[b];
    mnew[i] = g * m[i] + (1.f - g) * (mm[i] + tmp[i]);
}

// ---------------- launch ----------------
extern "C" void kernel_launch(void* const* d_in, const int* in_sizes, int n_in,
                              void* d_out, int out_size)
{
    const float* c    = (const float*)d_in[0];
    const float* m    = (const float*)d_in[1];
    const float* k    = (const float*)d_in[2];
    const float* q    = (const float*)d_in[3];
    const float* cw   = (const float*)d_in[4];
    const int*   mask = (const int*)  d_in[5];
    const float* cs   = (const float*)d_in[6];
    const float* ms   = (const float*)d_in[7];
    const float* Wcq  = (const float*)d_in[8];
    const float* bcq  = (const float*)d_in[9];
    const float* Wca  = (const float*)d_in[10];
    const float* bca  = (const float*)d_in[11];
    const float* Wm_r = (const float*)d_in[12];
    const float* bm_r = (const float*)d_in[13];
    const float* Wk   = (const float*)d_in[14];
    const float* bk   = (const float*)d_in[15];
    const float* WI   = (const float*)d_in[16];
    const float* bI   = (const float*)d_in[17];
    const float* Wra  = (const float*)d_in[18];
    const float* bra  = (const float*)d_in[19];
    const float* Wm_w = (const float*)d_in[20];
    const float* bm_w = (const float*)d_in[21];
    const float* Wsa  = (const float*)d_in[22];
    const float* bsa  = (const float*)d_in[23];
    const float* Wm2  = (const float*)d_in[24];
    const float* bm2  = (const float*)d_in[25];
    const float* Wc   = (const float*)d_in[26];
    const float* bc   = (const float*)d_in[27];
    const float* Ws   = (const float*)d_in[28];

    float* out      = (float*)d_out;
    float* out_cnew = out;                       // [B,D]
    float* out_mnew = out + 131072;              // [B,D]
    float* out_cv   = out + 262144;              // [B,L]
    float* out_rv   = out + 270336;              // [B,D,H,W]

    __nv_bfloat16 *p_kT2, *p_I2, *p_J2, *p_Wk2, *p_WI2, *p_Wra2;
    float *p_ra, *p_cq, *p_mI, *p_r, *p_mprev, *p_mm, *p_msa, *p_tmp, *p_gate;
    cudaGetSymbolAddress((void**)&p_kT2,  g_kT2);
    cudaGetSymbolAddress((void**)&p_I2,   g_I2);
    cudaGetSymbolAddress((void**)&p_J2,   g_J2);
    cudaGetSymbolAddress((void**)&p_Wk2,  g_Wk2);
    cudaGetSymbolAddress((void**)&p_WI2,  g_WI2);
    cudaGetSymbolAddress((void**)&p_Wra2, g_Wra2);
    cudaGetSymbolAddress((void**)&p_ra,   g_ra);
    cudaGetSymbolAddress((void**)&p_cq,   g_cq);
    cudaGetSymbolAddress((void**)&p_mI,   g_mI);
    cudaGetSymbolAddress((void**)&p_r,    g_r);
    cudaGetSymbolAddress((void**)&p_mprev,g_mprev);
    cudaGetSymbolAddress((void**)&p_mm,   g_mm);
    cudaGetSymbolAddress((void**)&p_msa,  g_msa);
    cudaGetSymbolAddress((void**)&p_tmp,  g_tmp);
    cudaGetSymbolAddress((void**)&p_gate, g_gate);

    cudaFuncSetAttribute(mma_gemm<512,  false, 0>, cudaFuncAttributeMaxDynamicSharedMemorySize, MG_SMEM);
    cudaFuncSetAttribute(mma_gemm<1024, true,  0>, cudaFuncAttributeMaxDynamicSharedMemorySize, MG_SMEM);
    cudaFuncSetAttribute(mma_gemm<512,  false, 1>, cudaFuncAttributeMaxDynamicSharedMemorySize, MG_SMEM);
    cudaFuncSetAttribute(softmax_rv_kernel, cudaFuncAttributeMaxDynamicSharedMemorySize, SMRV_SMEM);

    // ---- ordered so my 4th launch = mma_gemm I (ncu -s 5 -c 1 visibility) ----
    // 1. Wk -> hi/lo
    split_w_kernel<<<(DIM*DIM + 255)/256, 256>>>(Wk, p_Wk2, DIM, DIM);
    // 2. k -> kT hi/lo
    transpose_split_k<<<dim3(7, 16, BATCH), dim3(32, 8)>>>(k, p_kT2);
    // 3. mI = m @ Wm_r^T + bm_r
    gemm_small<512, false><<<dim3(8, 4), 256>>>(m, nullptr, Wm_r, bm_r, p_mI);
    // 4. I = mI ⊙ (kT @ Wk^T + bk) -> hi/lo          [HMMA]  << profiled
    mma_gemm<512, false, 0><<<dim3(4, 392), 256, MG_SMEM>>>(
        p_kT2, nullptr, p_Wk2, bk, p_mI, p_I2, nullptr);
    // 5. WI -> hi/lo
    split_w_kernel<<<(DIM*2*DIM + 255)/256, 256>>>(WI, p_WI2, DIM, 2*DIM);
    // 6. cq = [c|q] @ Wcq^T + bcq
    gemm_small<1024, true><<<dim3(8, 4), 256>>>(c, q, Wcq, bcq, p_cq);
    // 7. ControlUnit tail -> cv, c_new
    control_kernel<<<BATCH, 256>>>(p_cq, cw, mask, Wca, bca, out_cv, out_cnew);
    // 8. J = c_new ⊙ ([I|kT] @ WI^T + bI) -> hi/lo   [HMMA]
    mma_gemm<1024, true, 0><<<dim3(4, 392), 256, MG_SMEM>>>(
        p_I2, p_kT2, p_WI2, bI, out_cnew, p_J2, nullptr);
    // 9. Wra -> hi/lo
    split_w_kernel<<<(DIM*DIM + 255)/256, 256>>>(Wra, p_Wra2, DIM, DIM);
    // 10. ra = J @ Wra^T + bra -> fp32               [HMMA]
    mma_gemm<512, false, 1><<<dim3(4, 392), 256, MG_SMEM>>>(
        p_J2, nullptr, p_Wra2, bra, nullptr, nullptr, p_ra);
    // 11. rv = softmax_c(ra) -> d_out (transposed), r = sum_p rv*k
    softmax_rv_kernel<<<BATCH, 512, SMRV_SMEM>>>(p_ra, p_kT2, out_rv, p_r);
    // 12. m_prev = [r|m] @ Wm_w^T + bm_w
    gemm_small<1024, true><<<dim3(8, 4), 256>>>(p_r, m, Wm_w, bm_w, p_mprev);
    // 13. m_ = m_prev @ Wm2^T + bm2
    gemm_small<512, false><<<dim3(8, 4), 256>>>(p_mprev, nullptr, Wm2, bm2, p_mm);
    // 14. gate, sa softmax, m_sa
    gate_sa_kernel<<<BATCH, 256>>>(out_cnew, Wc, bc, cs, Wsa, bsa, ms, p_gate, p_msa);
    // 15. tmp = m_sa @ Ws^T
    gemm_small<512, false><<<dim3(8, 4), 256>>>(p_msa, nullptr, Ws, nullptr, p_tmp);
    // 16. m_new = gate*m + (1-gate)*(m_ + tmp)
    final_kernel<<<(BATCH * DIM) / 256, 256>>>(m, p_mm, p_tmp, p_gate, out_mnew);
}